// round 2
// baseline (speedup 1.0000x reference)
#include <cuda_runtime.h>
#include <math.h>

#define B_ 16
#define L_ 2048
#define D_ 256

// Scratch (static device arrays — no allocation allowed)
__device__ float g_emb[(size_t)B_ * L_ * D_];      // [B][L][D]
__device__ float g_hidden[(size_t)B_ * L_ * D_];   // [B][L][D] (post-LayerNorm)
__device__ float g_WT[512 * D_];                   // [k=512][n=256], k<256 -> Wn, else Wi

__device__ __forceinline__ float softplusf_(float x) {
    return fmaxf(x, 0.f) + log1pf(__expf(-fabsf(x)));
}
__device__ __forceinline__ float sigmoidf_(float x) {
    return 1.f / (1.f + __expf(-x));
}

// ---------------------------------------------------------------------------
// Kernel 1: temporal positional encoding
// emb[b,j,d] = sin(t/pv) if d even else cos(t/pv), pv = 10000^(2d/D)
// ---------------------------------------------------------------------------
__global__ void emb_kernel(const float* __restrict__ et) {
    int idx = blockIdx.x * blockDim.x + threadIdx.x;   // B*L*D threads
    int d   = idx & (D_ - 1);
    int bl  = idx >> 8;
    float t = et[bl];
    // t / 10000^(2d/256) = t * 2^(-log2(10000)/128 * d)
    float a = t * exp2f(-0.10381025296522991f * (float)d);
    g_emb[idx] = (d & 1) ? cosf(a) : sinf(a);
}

// ---------------------------------------------------------------------------
// Kernel 1b: pack [Wn | Wi] transposed -> g_WT[k][n] so kernel 3 loads coalesce
// ---------------------------------------------------------------------------
__global__ void wt_kernel(const float* __restrict__ Wn, const float* __restrict__ Wi) {
    int idx = blockIdx.x * blockDim.x + threadIdx.x;   // 512*256 threads
    int k = idx >> 8;
    int n = idx & 255;
    g_WT[idx] = (k < 256) ? Wn[n * 256 + k] : Wi[n * 256 + (k - 256)];
}

// ---------------------------------------------------------------------------
// Kernel 2: hidden[b,i,:] = LN( sum_{j<=i} score(t_i,t_j) * emb[b,j,:] )
// Block: 32 i-rows x full D=256. 256 threads; warp = 4 i-rows, lane = 8 d's.
// K-loop over j in chunks of 32, triangular skip. Scores computed on the fly.
// ---------------------------------------------------------------------------
__global__ __launch_bounds__(256, 2) void k2_scores_gemm_ln(
    const float* __restrict__ et, const float* __restrict__ gp,
    const float* __restrict__ lsc, const float* __restrict__ gamma,
    const float* __restrict__ beta)
{
    __shared__ float emb_sh[32][256];   // 32 KB
    __shared__ float sc_sh[32][36];     // transposed scores [j][i], padded

    const int b    = blockIdx.y;
    const int ib   = (int)gridDim.x - 1 - (int)blockIdx.x;  // heavy blocks first
    const int i0   = ib * 32;
    const int tid  = threadIdx.x;
    const int warp = tid >> 5;
    const int lane = tid & 31;

    const float ls      = softplusf_(lsc[0]);
    const float inv_ls2 = 1.f / (ls * ls);
    const float lpar    = sigmoidf_(gp[0]);
    const float inv_s   = 1.f / sigmoidf_(gp[1]);

    float acc[4][8];
#pragma unroll
    for (int r = 0; r < 4; ++r)
#pragma unroll
        for (int q = 0; q < 8; ++q) acc[r][q] = 0.f;

    const float ti = et[b * L_ + i0 + lane];   // i-index for score compute = lane
    const int nk = ib + 1;
    const float4* __restrict__ esrc = (const float4*)(g_emb + (size_t)b * L_ * D_);

    for (int kt = 0; kt < nk; ++kt) {
        const int j0 = kt * 32;
        // load emb tile [32 j][256 d] (coalesced float4)
        {
            float4* dst = (float4*)&emb_sh[0][0];
            const float4* src = esrc + (size_t)j0 * 64;
#pragma unroll
            for (int v = 0; v < 8; ++v) dst[tid + v * 256] = src[tid + v * 256];
        }
        // compute scores: this thread handles i = i0+lane, j = j0+warp*4+q
#pragma unroll
        for (int q = 0; q < 4; ++q) {
            const int jj = warp * 4 + q;
            const float tj = et[b * L_ + j0 + jj];
            const float dd = fabsf(ti - tj);
            const float kv = __expf(-dd * dd * inv_ls2);
            const float gv = 1.f + tanhf((dd * (1.f / 200.f) - lpar) * inv_s);
            float s = kv * gv;
            if (j0 + jj > i0 + lane) s = 0.f;   // causal mask (incl. diagonal)
            sc_sh[jj][lane] = s;                 // conflict-free: consecutive lanes
        }
        __syncthreads();
#pragma unroll
        for (int kk = 0; kk < 32; ++kk) {
            const float4 s4 = *(const float4*)&sc_sh[kk][warp * 4];  // broadcast
            const float4 e0 = *(const float4*)&emb_sh[kk][lane * 8];
            const float4 e1 = *(const float4*)&emb_sh[kk][lane * 8 + 4];
            const float sv[4] = {s4.x, s4.y, s4.z, s4.w};
            const float ev[8] = {e0.x, e0.y, e0.z, e0.w, e1.x, e1.y, e1.z, e1.w};
#pragma unroll
            for (int r = 0; r < 4; ++r)
#pragma unroll
                for (int q = 0; q < 8; ++q)
                    acc[r][q] = fmaf(sv[r], ev[q], acc[r][q]);
        }
        __syncthreads();
    }

    // Fused LayerNorm (each warp owns 4 full rows; 32 lanes x 8 d each)
    const float4 g0 = *(const float4*)&gamma[lane * 8];
    const float4 g1 = *(const float4*)&gamma[lane * 8 + 4];
    const float4 b0 = *(const float4*)&beta[lane * 8];
    const float4 b1 = *(const float4*)&beta[lane * 8 + 4];
    const float gv[8] = {g0.x, g0.y, g0.z, g0.w, g1.x, g1.y, g1.z, g1.w};
    const float bv[8] = {b0.x, b0.y, b0.z, b0.w, b1.x, b1.y, b1.z, b1.w};

#pragma unroll
    for (int r = 0; r < 4; ++r) {
        float sum = 0.f;
#pragma unroll
        for (int q = 0; q < 8; ++q) sum += acc[r][q];
#pragma unroll
        for (int off = 16; off > 0; off >>= 1)
            sum += __shfl_xor_sync(0xffffffffu, sum, off);
        const float mu = sum * (1.f / 256.f);
        float sq = 0.f;
#pragma unroll
        for (int q = 0; q < 8; ++q) { float dv = acc[r][q] - mu; sq = fmaf(dv, dv, sq); }
#pragma unroll
        for (int off = 16; off > 0; off >>= 1)
            sq += __shfl_xor_sync(0xffffffffu, sq, off);
        const float rs = rsqrtf(sq * (1.f / 256.f) + 1e-6f);

        float o[8];
#pragma unroll
        for (int q = 0; q < 8; ++q) o[q] = (acc[r][q] - mu) * rs * gv[q] + bv[q];
        float* drow = g_hidden + (size_t)(b * L_ + i0 + warp * 4 + r) * D_ + lane * 8;
        *(float4*)drow       = make_float4(o[0], o[1], o[2], o[3]);
        *(float4*)(drow + 4) = make_float4(o[4], o[5], o[6], o[7]);
    }
}

// ---------------------------------------------------------------------------
// Kernel 3: out[b,i] = softplus( w_time . relu(noise@Wn^T + hidden@Wi^T) + b )
// Treated as X=[noise|hidden] (K=512) times g_WT, fused epilogue.
// ---------------------------------------------------------------------------
__global__ __launch_bounds__(256, 2) void k3_generator(
    const float* __restrict__ noise, const float* __restrict__ wt,
    const float* __restrict__ btime, float* __restrict__ out)
{
    __shared__ float w_sh[32][256];   // W tile [kk][n]
    __shared__ float x_sh[32][36];    // X tile transposed [kk][i]

    const int b    = blockIdx.y;
    const int i0   = blockIdx.x * 32;
    const int tid  = threadIdx.x;
    const int warp = tid >> 5;
    const int lane = tid & 31;

    float acc[4][8];
#pragma unroll
    for (int r = 0; r < 4; ++r)
#pragma unroll
        for (int q = 0; q < 8; ++q) acc[r][q] = 0.f;

    const int xrow = tid >> 3;
    const int xc4  = (tid & 7) * 4;

    for (int kt = 0; kt < 16; ++kt) {
        const int k0 = kt * 32;
        {
            float4* dst = (float4*)&w_sh[0][0];
            const float4* src = (const float4*)g_WT + (size_t)k0 * 64;
#pragma unroll
            for (int v = 0; v < 8; ++v) dst[tid + v * 256] = src[tid + v * 256];
        }
        {
            const float* Xb = (kt < 8) ? noise : g_hidden;
            const int kc = (kt < 8) ? k0 : (k0 - 256);
            const float4 xv = *(const float4*)(Xb + (size_t)(b * L_ + i0 + xrow) * D_ + kc + xc4);
            x_sh[xc4 + 0][xrow] = xv.x;
            x_sh[xc4 + 1][xrow] = xv.y;
            x_sh[xc4 + 2][xrow] = xv.z;
            x_sh[xc4 + 3][xrow] = xv.w;
        }
        __syncthreads();
#pragma unroll
        for (int kk = 0; kk < 32; ++kk) {
            const float4 x4 = *(const float4*)&x_sh[kk][warp * 4];
            const float4 w0 = *(const float4*)&w_sh[kk][lane * 8];
            const float4 w1 = *(const float4*)&w_sh[kk][lane * 8 + 4];
            const float xv[4] = {x4.x, x4.y, x4.z, x4.w};
            const float wv[8] = {w0.x, w0.y, w0.z, w0.w, w1.x, w1.y, w1.z, w1.w};
#pragma unroll
            for (int r = 0; r < 4; ++r)
#pragma unroll
                for (int q = 0; q < 8; ++q)
                    acc[r][q] = fmaf(xv[r], wv[q], acc[r][q]);
        }
        __syncthreads();
    }

    // epilogue: relu, dot with w_time, softplus
    const float4 w0 = *(const float4*)&wt[lane * 8];
    const float4 w1 = *(const float4*)&wt[lane * 8 + 4];
    const float wv[8] = {w0.x, w0.y, w0.z, w0.w, w1.x, w1.y, w1.z, w1.w};
    const float bt = btime[0];

#pragma unroll
    for (int r = 0; r < 4; ++r) {
        float p = 0.f;
#pragma unroll
        for (int q = 0; q < 8; ++q) p = fmaf(wv[q], fmaxf(acc[r][q], 0.f), p);
#pragma unroll
        for (int off = 16; off > 0; off >>= 1)
            p += __shfl_xor_sync(0xffffffffu, p, off);
        if (lane == 0)
            out[b * L_ + i0 + warp * 4 + r] = softplusf_(p + bt);
    }
}

// ---------------------------------------------------------------------------
// Input order (metadata): 0 event_type (unused), 1 event_time, 2 noise,
// 3 gate_params, 4 length_scale, 5 Wn, 6 Wi, 7 w_time, 8 b_time,
// 9 ln_gamma, 10 ln_beta. Output: float32 [16,2048].
// ---------------------------------------------------------------------------
extern "C" void kernel_launch(void* const* d_in, const int* in_sizes, int n_in,
                              void* d_out, int out_size) {
    const float* et    = (const float*)d_in[1];
    const float* noise = (const float*)d_in[2];
    const float* gp    = (const float*)d_in[3];
    const float* lsc   = (const float*)d_in[4];
    const float* Wn    = (const float*)d_in[5];
    const float* Wi    = (const float*)d_in[6];
    const float* wt    = (const float*)d_in[7];
    const float* bt    = (const float*)d_in[8];
    const float* gam   = (const float*)d_in[9];
    const float* bet   = (const float*)d_in[10];
    float* out = (float*)d_out;

    emb_kernel<<<(B_ * L_ * D_) / 256, 256>>>(et);
    wt_kernel<<<(512 * 256) / 256, 256>>>(Wn, Wi);
    k2_scores_gemm_ln<<<dim3(L_ / 32, B_), 256>>>(et, gp, lsc, gam, bet);
    k3_generator<<<dim3(L_ / 32, B_), 256>>>(noise, wt, bt, out);
}

// round 3
// speedup vs baseline: 1.4874x; 1.4874x over previous
#include <cuda_runtime.h>
#include <math.h>

#define B_ 16
#define L_ 2048
#define D_ 256

// Scratch (static device arrays — no allocation allowed)
__device__ float g_emb[(size_t)B_ * L_ * D_];      // [B][L][D]
__device__ float g_hidden[(size_t)B_ * L_ * D_];   // [B][L][D] (post-LayerNorm)
__device__ float g_WT[512 * D_];                   // [k=512][n=256], k<256 -> Wn, else Wi

__device__ __forceinline__ float softplusf_(float x) {
    return fmaxf(x, 0.f) + log1pf(__expf(-fabsf(x)));
}
__device__ __forceinline__ float sigmoidf_(float x) {
    return 1.f / (1.f + __expf(-x));
}

// ---- packed fp32x2 helpers (Blackwell FFMA2 path; ptxas won't auto-fuse) ----
typedef unsigned long long u64;
__device__ __forceinline__ u64 pack2(float lo, float hi) {
    u64 r; asm("mov.b64 %0, {%1, %2};" : "=l"(r) : "f"(lo), "f"(hi)); return r;
}
__device__ __forceinline__ void unpack2(u64 v, float& lo, float& hi) {
    asm("mov.b64 {%0, %1}, %2;" : "=f"(lo), "=f"(hi) : "l"(v));
}
__device__ __forceinline__ void ffma2(u64& d, u64 a, u64 b) {
    asm("fma.rn.f32x2 %0, %1, %2, %0;" : "+l"(d) : "l"(a), "l"(b));
}

// ---------------------------------------------------------------------------
// Kernel 1: temporal positional encoding
// ---------------------------------------------------------------------------
__global__ void emb_kernel(const float* __restrict__ et) {
    int idx = blockIdx.x * blockDim.x + threadIdx.x;   // B*L*D threads
    int d   = idx & (D_ - 1);
    int bl  = idx >> 8;
    float t = et[bl];
    float a = t * exp2f(-0.10381025296522991f * (float)d);
    g_emb[idx] = (d & 1) ? cosf(a) : sinf(a);
}

// ---------------------------------------------------------------------------
// Kernel 1b: pack [Wn | Wi] transposed -> g_WT[k][n]
// ---------------------------------------------------------------------------
__global__ void wt_kernel(const float* __restrict__ Wn, const float* __restrict__ Wi) {
    int idx = blockIdx.x * blockDim.x + threadIdx.x;   // 512*256 threads
    int k = idx >> 8;
    int n = idx & 255;
    g_WT[idx] = (k < 256) ? Wn[n * 256 + k] : Wi[n * 256 + (k - 256)];
}

// ---------------------------------------------------------------------------
// Kernel 2: hidden = LN( tril(score) @ emb )
// Block: 64 i-rows x 256 d, 256 threads (8 warps). Warp w owns rows w*8..w*8+7.
// Lane owns d in {lane*4..+3} U {128+lane*4..+3}  (conflict-free LDS.128).
// Accumulators are packed f32x2 pairs; inner product uses FFMA2.
// ---------------------------------------------------------------------------
__global__ __launch_bounds__(256, 2) void k2_scores_gemm_ln(
    const float* __restrict__ et, const float* __restrict__ gp,
    const float* __restrict__ lsc, const float* __restrict__ gamma,
    const float* __restrict__ beta)
{
    __shared__ float emb_sh[32][256];     // 32 KB: [j][d]
    __shared__ float sc_sh[32][68];       // scores transposed [j][i_loc], pitch 68 (16B-aligned rows)

    const int b    = blockIdx.y;
    const int ib   = (int)gridDim.x - 1 - (int)blockIdx.x;  // heavy blocks first
    const int i0   = ib * 64;
    const int tid  = threadIdx.x;
    const int warp = tid >> 5;
    const int lane = tid & 31;

    const float ls      = softplusf_(lsc[0]);
    const float inv_ls2 = 1.f / (ls * ls);
    const float lpar    = sigmoidf_(gp[0]);
    const float inv_s   = 1.f / sigmoidf_(gp[1]);

    u64 acc[8][4];
#pragma unroll
    for (int r = 0; r < 8; ++r)
#pragma unroll
        for (int p = 0; p < 4; ++p) acc[r][p] = 0ull;

    // score-compute mapping: thread covers i = i0 + (tid&63), j = j0 + (tid>>6)*8 + q
    const int iloc = tid & 63;
    const int jgrp = (tid >> 6) * 8;
    const float ti = et[b * L_ + i0 + iloc];

    const int nk = 2 * ib + 2;
    const float4* __restrict__ esrc = (const float4*)(g_emb + (size_t)b * L_ * D_);

    for (int kt = 0; kt < nk; ++kt) {
        const int j0 = kt * 32;
        // load emb tile [32 j][256 d] (coalesced float4: 2048 float4 / 256 thr)
        {
            float4* dst = (float4*)&emb_sh[0][0];
            const float4* src = esrc + (size_t)j0 * 64;
#pragma unroll
            for (int v = 0; v < 8; ++v) dst[tid + v * 256] = src[tid + v * 256];
        }
        // compute 8 scores per thread
#pragma unroll
        for (int q = 0; q < 8; ++q) {
            const int jj = jgrp + q;
            const float tj = et[b * L_ + j0 + jj];
            const float dd = fabsf(ti - tj);
            const float kv = __expf(-dd * dd * inv_ls2);
            const float gv = 1.f + tanhf((dd * (1.f / 200.f) - lpar) * inv_s);
            float s = kv * gv;
            if (j0 + jj > i0 + iloc) s = 0.f;   // causal mask (incl. diagonal)
            sc_sh[jj][iloc] = s;                 // consecutive lanes -> consecutive banks
        }
        __syncthreads();
#pragma unroll
        for (int kk = 0; kk < 32; ++kk) {
            // emb pairs: contiguous 512B per LDS.128 -> conflict-free
            const ulonglong2 e01 = *(const ulonglong2*)&emb_sh[kk][lane * 4];
            const ulonglong2 e23 = *(const ulonglong2*)&emb_sh[kk][128 + lane * 4];
            // 8 scores for this warp's rows (broadcast loads)
            const float4 sA = *(const float4*)&sc_sh[kk][warp * 8];
            const float4 sB = *(const float4*)&sc_sh[kk][warp * 8 + 4];
            u64 s2[8];
            s2[0] = pack2(sA.x, sA.x); s2[1] = pack2(sA.y, sA.y);
            s2[2] = pack2(sA.z, sA.z); s2[3] = pack2(sA.w, sA.w);
            s2[4] = pack2(sB.x, sB.x); s2[5] = pack2(sB.y, sB.y);
            s2[6] = pack2(sB.z, sB.z); s2[7] = pack2(sB.w, sB.w);
#pragma unroll
            for (int r = 0; r < 8; ++r) {
                ffma2(acc[r][0], s2[r], e01.x);
                ffma2(acc[r][1], s2[r], e01.y);
                ffma2(acc[r][2], s2[r], e23.x);
                ffma2(acc[r][3], s2[r], e23.y);
            }
        }
        __syncthreads();
    }

    // Fused LayerNorm. Warp w owns rows i0 + w*8 + r; lane's d-cols per mapping.
    const float4 g0 = *(const float4*)&gamma[lane * 4];
    const float4 g1 = *(const float4*)&gamma[128 + lane * 4];
    const float4 b0 = *(const float4*)&beta[lane * 4];
    const float4 b1 = *(const float4*)&beta[128 + lane * 4];
    const float gv[8] = {g0.x, g0.y, g0.z, g0.w, g1.x, g1.y, g1.z, g1.w};
    const float bv[8] = {b0.x, b0.y, b0.z, b0.w, b1.x, b1.y, b1.z, b1.w};

#pragma unroll
    for (int r = 0; r < 8; ++r) {
        float v[8];
        unpack2(acc[r][0], v[0], v[1]);
        unpack2(acc[r][1], v[2], v[3]);
        unpack2(acc[r][2], v[4], v[5]);
        unpack2(acc[r][3], v[6], v[7]);

        float sum = 0.f;
#pragma unroll
        for (int q = 0; q < 8; ++q) sum += v[q];
#pragma unroll
        for (int off = 16; off > 0; off >>= 1)
            sum += __shfl_xor_sync(0xffffffffu, sum, off);
        const float mu = sum * (1.f / 256.f);
        float sq = 0.f;
#pragma unroll
        for (int q = 0; q < 8; ++q) { float dv = v[q] - mu; sq = fmaf(dv, dv, sq); }
#pragma unroll
        for (int off = 16; off > 0; off >>= 1)
            sq += __shfl_xor_sync(0xffffffffu, sq, off);
        const float rs = rsqrtf(sq * (1.f / 256.f) + 1e-6f);

        float o[8];
#pragma unroll
        for (int q = 0; q < 8; ++q) o[q] = (v[q] - mu) * rs * gv[q] + bv[q];
        float* drow = g_hidden + (size_t)(b * L_ + i0 + warp * 8 + r) * D_;
        *(float4*)(drow + lane * 4)       = make_float4(o[0], o[1], o[2], o[3]);
        *(float4*)(drow + 128 + lane * 4) = make_float4(o[4], o[5], o[6], o[7]);
    }
}

// ---------------------------------------------------------------------------
// Kernel 3: out = softplus( w_time . relu([noise|hidden] @ WT) + b )
// Same 64x256 tiling / f32x2 structure; K = 512.
// ---------------------------------------------------------------------------
__global__ __launch_bounds__(256, 2) void k3_generator(
    const float* __restrict__ noise, const float* __restrict__ wt,
    const float* __restrict__ btime, float* __restrict__ out)
{
    __shared__ float w_sh[32][256];   // [kk][n]
    __shared__ float x_sh[32][68];    // X transposed [kk][i_loc]

    const int b    = blockIdx.y;
    const int i0   = blockIdx.x * 64;
    const int tid  = threadIdx.x;
    const int warp = tid >> 5;
    const int lane = tid & 31;

    u64 acc[8][4];
#pragma unroll
    for (int r = 0; r < 8; ++r)
#pragma unroll
        for (int p = 0; p < 4; ++p) acc[r][p] = 0ull;

    const int iloc = tid & 63;          // X-load row
    const int kq   = (tid >> 6) * 8;    // X-load k-offset (8 values = 2 float4)

    for (int kt = 0; kt < 16; ++kt) {
        const int k0 = kt * 32;
        // W tile (coalesced)
        {
            float4* dst = (float4*)&w_sh[0][0];
            const float4* src = (const float4*)g_WT + (size_t)k0 * 64;
#pragma unroll
            for (int v = 0; v < 8; ++v) dst[tid + v * 256] = src[tid + v * 256];
        }
        // X tile: [64 i][32 k] -> transposed smem; consecutive lanes write consecutive i
        {
            const float* Xb = (kt < 8) ? noise : g_hidden;
            const int kc = (kt < 8) ? k0 : (k0 - 256);
            const float* xr = Xb + (size_t)(b * L_ + i0 + iloc) * D_ + kc + kq;
            const float4 xa = *(const float4*)xr;
            const float4 xb2 = *(const float4*)(xr + 4);
            x_sh[kq + 0][iloc] = xa.x;  x_sh[kq + 1][iloc] = xa.y;
            x_sh[kq + 2][iloc] = xa.z;  x_sh[kq + 3][iloc] = xa.w;
            x_sh[kq + 4][iloc] = xb2.x; x_sh[kq + 5][iloc] = xb2.y;
            x_sh[kq + 6][iloc] = xb2.z; x_sh[kq + 7][iloc] = xb2.w;
        }
        __syncthreads();
#pragma unroll
        for (int kk = 0; kk < 32; ++kk) {
            const ulonglong2 w01 = *(const ulonglong2*)&w_sh[kk][lane * 4];
            const ulonglong2 w23 = *(const ulonglong2*)&w_sh[kk][128 + lane * 4];
            const float4 xA = *(const float4*)&x_sh[kk][warp * 8];
            const float4 xB = *(const float4*)&x_sh[kk][warp * 8 + 4];
            u64 x2[8];
            x2[0] = pack2(xA.x, xA.x); x2[1] = pack2(xA.y, xA.y);
            x2[2] = pack2(xA.z, xA.z); x2[3] = pack2(xA.w, xA.w);
            x2[4] = pack2(xB.x, xB.x); x2[5] = pack2(xB.y, xB.y);
            x2[6] = pack2(xB.z, xB.z); x2[7] = pack2(xB.w, xB.w);
#pragma unroll
            for (int r = 0; r < 8; ++r) {
                ffma2(acc[r][0], x2[r], w01.x);
                ffma2(acc[r][1], x2[r], w01.y);
                ffma2(acc[r][2], x2[r], w23.x);
                ffma2(acc[r][3], x2[r], w23.y);
            }
        }
        __syncthreads();
    }

    // epilogue: relu, dot with w_time, softplus
    const float4 w0 = *(const float4*)&wt[lane * 4];
    const float4 w1 = *(const float4*)&wt[128 + lane * 4];
    const float wv[8] = {w0.x, w0.y, w0.z, w0.w, w1.x, w1.y, w1.z, w1.w};
    const float bt = btime[0];

#pragma unroll
    for (int r = 0; r < 8; ++r) {
        float v[8];
        unpack2(acc[r][0], v[0], v[1]);
        unpack2(acc[r][1], v[2], v[3]);
        unpack2(acc[r][2], v[4], v[5]);
        unpack2(acc[r][3], v[6], v[7]);
        float p = 0.f;
#pragma unroll
        for (int q = 0; q < 8; ++q) p = fmaf(wv[q], fmaxf(v[q], 0.f), p);
#pragma unroll
        for (int off = 16; off > 0; off >>= 1)
            p += __shfl_xor_sync(0xffffffffu, p, off);
        if (lane == 0)
            out[b * L_ + i0 + warp * 8 + r] = softplusf_(p + bt);
    }
}

// ---------------------------------------------------------------------------
// Input order: 0 event_type (unused), 1 event_time, 2 noise, 3 gate_params,
// 4 length_scale, 5 Wn, 6 Wi, 7 w_time, 8 b_time, 9 ln_gamma, 10 ln_beta.
// ---------------------------------------------------------------------------
extern "C" void kernel_launch(void* const* d_in, const int* in_sizes, int n_in,
                              void* d_out, int out_size) {
    const float* et    = (const float*)d_in[1];
    const float* noise = (const float*)d_in[2];
    const float* gp    = (const float*)d_in[3];
    const float* lsc   = (const float*)d_in[4];
    const float* Wn    = (const float*)d_in[5];
    const float* Wi    = (const float*)d_in[6];
    const float* wt    = (const float*)d_in[7];
    const float* bt    = (const float*)d_in[8];
    const float* gam   = (const float*)d_in[9];
    const float* bet   = (const float*)d_in[10];
    float* out = (float*)d_out;

    emb_kernel<<<(B_ * L_ * D_) / 256, 256>>>(et);
    wt_kernel<<<(512 * 256) / 256, 256>>>(Wn, Wi);
    k2_scores_gemm_ln<<<dim3(L_ / 64, B_), 256>>>(et, gp, lsc, gam, bet);
    k3_generator<<<dim3(L_ / 64, B_), 256>>>(noise, wt, bt, out);
}

// round 7
// speedup vs baseline: 2.2835x; 1.5352x over previous
#include <cuda_runtime.h>
#include <math.h>
#include <stdint.h>

#define B_ 16
#define L_ 2048
#define D_ 256

// Scratch (static device arrays — no allocation allowed)
__device__ float g_embT[(size_t)B_ * D_ * L_];   // [B][D][L], j k-interleaved, tf32-rounded
__device__ float g_hidden[(size_t)B_ * L_ * D_]; // [B][L][D], d k-interleaved, tf32-rounded
__device__ float g_Wp[256 * 512];                // [n][k=512], k-interleaved, tf32-rounded

// ---------------------------------------------------------------------------
// helpers
// ---------------------------------------------------------------------------
__device__ __forceinline__ float softplusf_(float x) {
    return fmaxf(x, 0.f) + log1pf(__expf(-fabsf(x)));
}
__device__ __forceinline__ float sigmoidf_(float x) {
    return 1.f / (1.f + __expf(-x));
}
__device__ __forceinline__ uint32_t tf32r_(float x) {
    uint32_t r; asm("cvt.rna.tf32.f32 %0, %1;" : "=r"(r) : "f"(x)); return r;
}
// K-interleave within 8-blocks: logical l -> phys (so frag regs k and k+4 are adjacent)
__device__ __forceinline__ int kperm_(int l) {
    return (l & ~7) | (2 * (l & 3) + ((l >> 2) & 1));
}
#define SW128_(x) ((x) ^ (((x) >> 3) & 0x70))

__device__ __forceinline__ void mma8_(float* c, uint32_t a0, uint32_t a1, uint32_t a2,
                                      uint32_t a3, uint32_t b0, uint32_t b1) {
    asm volatile(
        "mma.sync.aligned.m16n8k8.row.col.f32.tf32.tf32.f32 "
        "{%0,%1,%2,%3}, {%4,%5,%6,%7}, {%8,%9}, {%0,%1,%2,%3};"
        : "+f"(c[0]), "+f"(c[1]), "+f"(c[2]), "+f"(c[3])
        : "r"(a0), "r"(a1), "r"(a2), "r"(a3), "r"(b0), "r"(b1));
}

// smem byte layout (dynamic, 51200 B): A 16KB | B 32KB | params 2KB
#define OFF_A   0
#define OFF_B   16384
#define OFF_PRM 49152
#define SM_TOT  51200

// ---------------------------------------------------------------------------
// prep: transposed + k-interleaved + tf32-rounded positional embedding
// ---------------------------------------------------------------------------
__global__ void embT_kernel(const float* __restrict__ et) {
    int idx = blockIdx.x * 256 + threadIdx.x;   // B*D*L
    int j   = idx & (L_ - 1);
    int d   = (idx >> 11) & (D_ - 1);
    int b   = idx >> 19;
    float t = __ldg(&et[b * L_ + j]);
    float a = t * exp2f(-0.10381025296522991f * (float)d);
    float v = (d & 1) ? cosf(a) : sinf(a);
    g_embT[(size_t)b * D_ * L_ + (size_t)d * L_ + kperm_(j)] = __uint_as_float(tf32r_(v));
}

// prep: pack [Wn | Wi] -> g_Wp[n][512], k-interleaved, tf32-rounded
__global__ void wp_kernel(const float* __restrict__ Wn, const float* __restrict__ Wi) {
    int idx = blockIdx.x * 256 + threadIdx.x;   // 256*512
    int n = idx >> 9, k = idx & 511;
    float v = (k < 256) ? Wn[n * 256 + k] : Wi[n * 256 + (k - 256)];
    g_Wp[n * 512 + kperm_(k)] = __uint_as_float(tf32r_(v));
}

// ---------------------------------------------------------------------------
// k2: hidden = LN( tril(score) @ emb ) — tf32 mma.sync, 128x256 block tile
// ---------------------------------------------------------------------------
__global__ __launch_bounds__(512) void k2_mma(
    const float* __restrict__ et, const float* __restrict__ gp,
    const float* __restrict__ lsc, const float* __restrict__ gamma,
    const float* __restrict__ beta)
{
    extern __shared__ char sm[];
    char* Ab = sm + OFF_A;
    char* Bb = sm + OFF_B;
    float* gsm = (float*)(sm + OFF_PRM);
    float* bsm = gsm + 256;
    float* ps = (float*)sm;        // alias A-region after mainloop
    float* pq = ps + 512;

    const int tid = threadIdx.x, lane = tid & 31, warp = tid >> 5;
    const int g = lane >> 2, t = lane & 3, wm = warp >> 2, wn = warp & 3;
    if (tid < 256) { gsm[tid] = gamma[tid]; bsm[tid] = beta[tid]; }

    const int b  = blockIdx.y;
    const int ib = (int)gridDim.x - 1 - (int)blockIdx.x;  // heavy blocks first
    const int i0 = ib * 128;

    const float ls      = softplusf_(lsc[0]);
    const float inv_ls2 = 1.f / (ls * ls);
    const float inv_s   = 1.f / sigmoidf_(gp[1]);
    const float c1      = inv_s * 0.005f;
    const float c0      = -sigmoidf_(gp[0]) * inv_s;

    float acc[2][8][4];
#pragma unroll
    for (int mf = 0; mf < 2; ++mf)
#pragma unroll
        for (int nf = 0; nf < 8; ++nf)
#pragma unroll
            for (int e = 0; e < 4; ++e) acc[mf][nf][e] = 0.f;

    // score mapping: warp-uniform i rows, lane-indexed j column
    const int jlog = tid & 31;
    const int igrp = (tid >> 5) * 8;
    const int pjb  = kperm_(jlog) * 4;
    float tiv[8];
#pragma unroll
    for (int q = 0; q < 8; ++q) tiv[q] = __ldg(&et[b * L_ + i0 + igrp + q]);
    const float* __restrict__ ET = g_embT + (size_t)b * D_ * L_;

    const int nk = 4 * (ib + 1);
    for (int kt = 0; kt < nk; ++kt) {
        const int j0 = kt * 32;
        __syncthreads();
        // B tile: emb^T [256 d][32 j-phys] (float4 coalesced, SW128)
#pragma unroll
        for (int q = 0; q < 4; ++q) {
            const int v = tid + 512 * q;
            const int d_ = v >> 3, j4 = (v & 7) * 4;
            const float4 x = *(const float4*)(ET + (size_t)d_ * L_ + j0 + j4);
            *(float4*)(Bb + SW128_(d_ * 128 + j4 * 4)) = x;
        }
        // A tile: scores, conflict-free scalar stores
        {
            const float tj = __ldg(&et[b * L_ + j0 + jlog]);
#pragma unroll
            for (int q = 0; q < 8; ++q) {
                const float dd = fabsf(tiv[q] - tj);
                const float kv = __expf(-dd * dd * inv_ls2);
                float th;
                asm("tanh.approx.f32 %0, %1;" : "=f"(th) : "f"(fmaf(dd, c1, c0)));
                float s = fmaf(kv, th, kv);
                if (j0 + jlog > i0 + igrp + q) s = 0.f;   // causal (keep diagonal)
                *(uint32_t*)(Ab + SW128_((igrp + q) * 128 + pjb)) = tf32r_(s);
            }
        }
        __syncthreads();
#pragma unroll
        for (int kf = 0; kf < 4; ++kf) {
            const int kb = (8 * kf + 2 * t) * 4;
            uint32_t a[2][4];
#pragma unroll
            for (int mf = 0; mf < 2; ++mf) {
                const int r0 = wm * 32 + mf * 16 + g;
                const float2 v0 = *(const float2*)(Ab + SW128_(r0 * 128 + kb));
                const float2 v1 = *(const float2*)(Ab + SW128_((r0 + 8) * 128 + kb));
                a[mf][0] = __float_as_uint(v0.x); a[mf][2] = __float_as_uint(v0.y);
                a[mf][1] = __float_as_uint(v1.x); a[mf][3] = __float_as_uint(v1.y);
            }
#pragma unroll
            for (int nf = 0; nf < 8; ++nf) {
                const int n = wn * 64 + nf * 8 + g;
                const float2 bv = *(const float2*)(Bb + SW128_(n * 128 + kb));
                const uint32_t b0 = __float_as_uint(bv.x), b1 = __float_as_uint(bv.y);
                mma8_(acc[0][nf], a[0][0], a[0][1], a[0][2], a[0][3], b0, b1);
                mma8_(acc[1][nf], a[1][0], a[1][1], a[1][2], a[1][3], b0, b1);
            }
        }
    }
    __syncthreads();

    // LN partials: per-row sum/sumsq, quad-reduced, 4 wn-partials in smem
#pragma unroll
    for (int mf = 0; mf < 2; ++mf)
#pragma unroll
        for (int h = 0; h < 2; ++h) {
            float s = 0.f, q2 = 0.f;
#pragma unroll
            for (int nf = 0; nf < 8; ++nf) {
                const float v0 = acc[mf][nf][2 * h], v1 = acc[mf][nf][2 * h + 1];
                s += v0 + v1;
                q2 = fmaf(v0, v0, fmaf(v1, v1, q2));
            }
            s  += __shfl_xor_sync(0xffffffffu, s, 1);
            s  += __shfl_xor_sync(0xffffffffu, s, 2);
            q2 += __shfl_xor_sync(0xffffffffu, q2, 1);
            q2 += __shfl_xor_sync(0xffffffffu, q2, 2);
            if (t == 0) {
                const int r = wm * 32 + mf * 16 + h * 8 + g;
                ps[r * 4 + wn] = s; pq[r * 4 + wn] = q2;
            }
        }
    __syncthreads();

#pragma unroll
    for (int mf = 0; mf < 2; ++mf)
#pragma unroll
        for (int h = 0; h < 2; ++h) {
            const int r = wm * 32 + mf * 16 + h * 8 + g;
            const float su = ps[r * 4] + ps[r * 4 + 1] + ps[r * 4 + 2] + ps[r * 4 + 3];
            const float sq = pq[r * 4] + pq[r * 4 + 1] + pq[r * 4 + 2] + pq[r * 4 + 3];
            const float mu  = su * (1.f / 256.f);
            const float var = fmaxf(sq * (1.f / 256.f) - mu * mu, 0.f);
            const float rs  = rsqrtf(var + 1e-6f);
            float* dst = g_hidden + (size_t)(b * L_ + i0 + r) * 256;
#pragma unroll
            for (int nf = 0; nf < 8; ++nf)
#pragma unroll
                for (int e = 0; e < 2; ++e) {
                    const int c = wn * 64 + nf * 8 + 2 * t + e;
                    const float o = (acc[mf][nf][2 * h + e] - mu) * rs * gsm[c] + bsm[c];
                    dst[kperm_(c)] = __uint_as_float(tf32r_(o));  // k-interleaved for k3
                }
        }
}

// ---------------------------------------------------------------------------
// k3: out = softplus( w_time . relu([noise|hidden] @ [Wn;Wi]^T) + b )
// ---------------------------------------------------------------------------
__global__ __launch_bounds__(512) void k3_mma(
    const float* __restrict__ noise, const float* __restrict__ wt,
    const float* __restrict__ btime, float* __restrict__ out)
{
    extern __shared__ char sm[];
    char* Ab = sm + OFF_A;
    char* Bb = sm + OFF_B;
    float* wsm = (float*)(sm + OFF_PRM);
    float* pp = (float*)sm;   // alias A after mainloop

    const int tid = threadIdx.x, lane = tid & 31, warp = tid >> 5;
    const int g = lane >> 2, t = lane & 3, wm = warp >> 2, wn = warp & 3;
    if (tid < 256) wsm[tid] = wt[tid];

    const int b  = blockIdx.y;
    const int i0 = blockIdx.x * 128;

    float acc[2][8][4];
#pragma unroll
    for (int mf = 0; mf < 2; ++mf)
#pragma unroll
        for (int nf = 0; nf < 8; ++nf)
#pragma unroll
            for (int e = 0; e < 4; ++e) acc[mf][nf][e] = 0.f;

    for (int kt = 0; kt < 16; ++kt) {
        const int kc = kt * 32;
        __syncthreads();
        // B tile: W [256 n][32 k-phys]
#pragma unroll
        for (int q = 0; q < 4; ++q) {
            const int v = tid + 512 * q;
            const int n = v >> 3, j4 = (v & 7) * 4;
            const float4 x = *(const float4*)(g_Wp + n * 512 + kc + j4);
            *(float4*)(Bb + SW128_(n * 128 + j4 * 4)) = x;
        }
        // A tile: X [128 i][32 k]
        if (kt < 8) {   // noise: logical layout -> scalar scatter w/ perm + tf32 round
#pragma unroll
            for (int q = 0; q < 2; ++q) {
                const int v = tid + 512 * q;
                const int i_ = v >> 3, j4 = (v & 7) * 4;
                const float4 x = *(const float4*)(noise + (size_t)(b * L_ + i0 + i_) * 256 + kc + j4);
                const float xv[4] = {x.x, x.y, x.z, x.w};
#pragma unroll
                for (int e = 0; e < 4; ++e)
                    *(uint32_t*)(Ab + SW128_(i_ * 128 + kperm_(j4 + e) * 4)) = tf32r_(xv[e]);
            }
        } else {        // hidden: already k-interleaved + tf32-rounded
#pragma unroll
            for (int q = 0; q < 2; ++q) {
                const int v = tid + 512 * q;
                const int i_ = v >> 3, j4 = (v & 7) * 4;
                const float4 x = *(const float4*)(g_hidden + (size_t)(b * L_ + i0 + i_) * 256 + (kc - 256) + j4);
                *(float4*)(Ab + SW128_(i_ * 128 + j4 * 4)) = x;
            }
        }
        __syncthreads();
#pragma unroll
        for (int kf = 0; kf < 4; ++kf) {
            const int kb = (8 * kf + 2 * t) * 4;
            uint32_t a[2][4];
#pragma unroll
            for (int mf = 0; mf < 2; ++mf) {
                const int r0 = wm * 32 + mf * 16 + g;
                const float2 v0 = *(const float2*)(Ab + SW128_(r0 * 128 + kb));
                const float2 v1 = *(const float2*)(Ab + SW128_((r0 + 8) * 128 + kb));
                a[mf][0] = __float_as_uint(v0.x); a[mf][2] = __float_as_uint(v0.y);
                a[mf][1] = __float_as_uint(v1.x); a[mf][3] = __float_as_uint(v1.y);
            }
#pragma unroll
            for (int nf = 0; nf < 8; ++nf) {
                const int n = wn * 64 + nf * 8 + g;
                const float2 bv = *(const float2*)(Bb + SW128_(n * 128 + kb));
                const uint32_t b0 = __float_as_uint(bv.x), b1 = __float_as_uint(bv.y);
                mma8_(acc[0][nf], a[0][0], a[0][1], a[0][2], a[0][3], b0, b1);
                mma8_(acc[1][nf], a[1][0], a[1][1], a[1][2], a[1][3], b0, b1);
            }
        }
    }
    __syncthreads();

    // epilogue: relu + dot(w_time) partials -> quad reduce -> smem -> softplus
#pragma unroll
    for (int mf = 0; mf < 2; ++mf)
#pragma unroll
        for (int h = 0; h < 2; ++h) {
            float p = 0.f;
#pragma unroll
            for (int nf = 0; nf < 8; ++nf)
#pragma unroll
                for (int e = 0; e < 2; ++e) {
                    const int c = wn * 64 + nf * 8 + 2 * t + e;
                    p = fmaf(wsm[c], fmaxf(acc[mf][nf][2 * h + e], 0.f), p);
                }
            p += __shfl_xor_sync(0xffffffffu, p, 1);
            p += __shfl_xor_sync(0xffffffffu, p, 2);
            if (t == 0) pp[(wm * 32 + mf * 16 + h * 8 + g) * 4 + wn] = p;
        }
    __syncthreads();
    if (tid < 128) {
        const float s = pp[tid * 4] + pp[tid * 4 + 1] + pp[tid * 4 + 2] + pp[tid * 4 + 3];
        out[b * L_ + i0 + tid] = softplusf_(s + btime[0]);
    }
}

// ---------------------------------------------------------------------------
// Input order: 0 event_type (unused), 1 event_time, 2 noise, 3 gate_params,
// 4 length_scale, 5 Wn, 6 Wi, 7 w_time, 8 b_time, 9 ln_gamma, 10 ln_beta.
// ---------------------------------------------------------------------------
extern "C" void kernel_launch(void* const* d_in, const int* in_sizes, int n_in,
                              void* d_out, int out_size) {
    const float* et    = (const float*)d_in[1];
    const float* noise = (const float*)d_in[2];
    const float* gp    = (const float*)d_in[3];
    const float* lsc   = (const float*)d_in[4];
    const float* Wn    = (const float*)d_in[5];
    const float* Wi    = (const float*)d_in[6];
    const float* wt    = (const float*)d_in[7];
    const float* bt    = (const float*)d_in[8];
    const float* gam   = (const float*)d_in[9];
    const float* bet   = (const float*)d_in[10];
    float* out = (float*)d_out;

    cudaFuncSetAttribute(k2_mma, cudaFuncAttributeMaxDynamicSharedMemorySize, SM_TOT);
    cudaFuncSetAttribute(k3_mma, cudaFuncAttributeMaxDynamicSharedMemorySize, SM_TOT);

    embT_kernel<<<(B_ * D_ * L_) / 256, 256>>>(et);
    wp_kernel<<<(256 * 512) / 256, 256>>>(Wn, Wi);
    k2_mma<<<dim3(L_ / 128, B_), 512, SM_TOT>>>(et, gp, lsc, gam, bet);
    k3_mma<<<dim3(L_ / 128, B_), 512, SM_TOT>>>(noise, wt, bt, out);
}

// round 8
// speedup vs baseline: 2.4685x; 1.0810x over previous
#include <cuda_runtime.h>
#include <math.h>
#include <stdint.h>

#define B_ 16
#define L_ 2048
#define D_ 256

// Scratch (static device arrays — no allocation allowed)
__device__ float g_embT[(size_t)B_ * D_ * L_];   // [B][D][L], j k-interleaved, tf32-rounded
__device__ float g_hidden[(size_t)B_ * L_ * D_]; // [B][L][D], d k-interleaved, tf32-rounded
__device__ float g_noiseP[(size_t)B_ * L_ * D_]; // noise, k-interleaved, tf32-rounded
__device__ float g_Wp[256 * 512];                // [n][k=512], k-interleaved, tf32-rounded

// ---------------------------------------------------------------------------
// helpers
// ---------------------------------------------------------------------------
__device__ __forceinline__ float softplusf_(float x) {
    return fmaxf(x, 0.f) + log1pf(__expf(-fabsf(x)));
}
__device__ __forceinline__ float sigmoidf_(float x) {
    return 1.f / (1.f + __expf(-x));
}
__device__ __forceinline__ uint32_t tf32r_(float x) {
    uint32_t r; asm("cvt.rna.tf32.f32 %0, %1;" : "=r"(r) : "f"(x)); return r;
}
// K-interleave within 8-blocks (frag regs k and k+4 physically adjacent)
__device__ __forceinline__ int kperm_(int l) {
    return (l & ~7) | (2 * (l & 3) + ((l >> 2) & 1));
}
#define SW128_(x) ((x) ^ (((x) >> 3) & 0x70))

__device__ __forceinline__ uint32_t s2u_(const void* p) {
    uint32_t a;
    asm("{ .reg .u64 t; cvta.to.shared.u64 t, %1; cvt.u32.u64 %0, t; }" : "=r"(a) : "l"(p));
    return a;
}
__device__ __forceinline__ void cpa16_(uint32_t dst, const void* src) {
    asm volatile("cp.async.cg.shared.global [%0], [%1], 16;" :: "r"(dst), "l"(src) : "memory");
}
#define CPA_COMMIT_ asm volatile("cp.async.commit_group;" ::: "memory")
#define CPA_WAIT0_  asm volatile("cp.async.wait_group 0;" ::: "memory")

__device__ __forceinline__ void mma8_(float* c, uint32_t a0, uint32_t a1, uint32_t a2,
                                      uint32_t a3, uint32_t b0, uint32_t b1) {
    asm volatile(
        "mma.sync.aligned.m16n8k8.row.col.f32.tf32.tf32.f32 "
        "{%0,%1,%2,%3}, {%4,%5,%6,%7}, {%8,%9}, {%0,%1,%2,%3};"
        : "+f"(c[0]), "+f"(c[1]), "+f"(c[2]), "+f"(c[3])
        : "r"(a0), "r"(a1), "r"(a2), "r"(a3), "r"(b0), "r"(b1));
}

// smem byte layout (double-buffered): A 2x16KB | B 2x32KB | et 8KB | params 2KB
#define OFF_A0  0
#define OFF_A1  16384
#define OFF_B0  32768
#define OFF_B1  65536
#define OFF_ET  98304
#define OFF_PRM 106496
#define SM_TOT  108544

// ---------------------------------------------------------------------------
// prep kernels
// ---------------------------------------------------------------------------
__global__ void embT_kernel(const float* __restrict__ et) {
    int idx = blockIdx.x * 256 + threadIdx.x;   // B*D*L
    int j   = idx & (L_ - 1);
    int d   = (idx >> 11) & (D_ - 1);
    int b   = idx >> 19;
    float t = __ldg(&et[b * L_ + j]);
    float a = t * exp2f(-0.10381025296522991f * (float)d);
    float v = (d & 1) ? cosf(a) : sinf(a);
    g_embT[(size_t)b * D_ * L_ + (size_t)d * L_ + kperm_(j)] = __uint_as_float(tf32r_(v));
}

__global__ void wp_kernel(const float* __restrict__ Wn, const float* __restrict__ Wi) {
    int idx = blockIdx.x * 256 + threadIdx.x;   // 256*512
    int n = idx >> 9, k = idx & 511;
    float v = (k < 256) ? Wn[n * 256 + k] : Wi[n * 256 + (k - 256)];
    g_Wp[n * 512 + kperm_(k)] = __uint_as_float(tf32r_(v));
}

__global__ void np_kernel(const float* __restrict__ noise) {
    int idx = blockIdx.x * 256 + threadIdx.x;   // B*L*D
    int k = idx & 255, row = idx >> 8;
    g_noiseP[(size_t)row * 256 + kperm_(k)] = __uint_as_float(tf32r_(__ldg(&noise[idx])));
}

// ---------------------------------------------------------------------------
// k2: hidden = LN( tril(score) @ emb ) — tf32 mma.sync, pipelined
// ---------------------------------------------------------------------------
__global__ __launch_bounds__(512) void k2_mma(
    const float* __restrict__ et, const float* __restrict__ gp,
    const float* __restrict__ lsc, const float* __restrict__ gamma,
    const float* __restrict__ beta)
{
    extern __shared__ char sm[];
    const uint32_t sbase = s2u_(sm);
    float* ets = (float*)(sm + OFF_ET);
    float* gsm = (float*)(sm + OFF_PRM);
    float* bsm = gsm + 256;
    float* ps  = (float*)sm;   // alias A0 after mainloop
    float* pq  = ps + 512;

    const int tid = threadIdx.x, lane = tid & 31, warp = tid >> 5;
    const int g = lane >> 2, t = lane & 3, wm = warp >> 2, wn = warp & 3;
    if (tid < 256) { gsm[tid] = gamma[tid]; bsm[tid] = beta[tid]; }

    const int b  = blockIdx.y;
    const int ib = (int)gridDim.x - 1 - (int)blockIdx.x;  // heavy blocks first
    const int i0 = ib * 128;
    const int nk = 4 * (ib + 1);

    const float ls      = softplusf_(lsc[0]);
    const float inv_ls2 = 1.f / (ls * ls);
    const float inv_s   = 1.f / sigmoidf_(gp[1]);
    const float c1      = inv_s * 0.005f;
    const float c0      = -sigmoidf_(gp[0]) * inv_s;

    const int jlog = tid & 31;
    const int igrp = (tid >> 5) * 8;
    const int pjb  = kperm_(jlog) * 4;
    const float* __restrict__ ET = g_embT + (size_t)b * D_ * L_;

    // stage et[0 .. 128*(ib+1)) into smem once
    for (int v = tid; v < 128 * (ib + 1); v += 512) ets[v] = __ldg(&et[b * L_ + v]);

    // B-tile prefetch via cp.async
    const int bd_ = tid >> 3, bj4 = (tid & 7) * 4;
    auto prefB = [&](int kt, uint32_t boff) {
        const int j0 = kt * 32;
#pragma unroll
        for (int q = 0; q < 4; ++q) {
            const int d_ = bd_ + 64 * q;
            cpa16_(sbase + boff + SW128_(d_ * 128 + bj4 * 4),
                   ET + (size_t)d_ * L_ + j0 + bj4);
        }
        CPA_COMMIT_;
    };

    float acc[2][8][4];
#pragma unroll
    for (int mf = 0; mf < 2; ++mf)
#pragma unroll
        for (int nf = 0; nf < 8; ++nf)
#pragma unroll
            for (int e = 0; e < 4; ++e) acc[mf][nf][e] = 0.f;

    // prologue
    prefB(0, OFF_B0);
    __syncthreads();                       // ets visible
    float tiv[8];
#pragma unroll
    for (int q = 0; q < 8; ++q) tiv[q] = ets[i0 + igrp + q];

    auto scores = [&](int kt, uint32_t aoff) {
        const int j0 = kt * 32;
        const float tj = ets[j0 + jlog];
#pragma unroll
        for (int q = 0; q < 8; ++q) {
            const float dd = fabsf(tiv[q] - tj);
            const float kv = __expf(-dd * dd * inv_ls2);
            float th;
            asm("tanh.approx.f32 %0, %1;" : "=f"(th) : "f"(fmaf(dd, c1, c0)));
            float s = fmaf(kv, th, kv);
            if (j0 + jlog > i0 + igrp + q) s = 0.f;   // causal (keep diagonal)
            *(uint32_t*)(sm + aoff + SW128_((igrp + q) * 128 + pjb)) = tf32r_(s);
        }
    };

    scores(0, OFF_A0);
    CPA_WAIT0_;
    __syncthreads();                       // buffers 0 ready

    for (int kt = 0; kt < nk; ++kt) {
        const int s = kt & 1;
        const uint32_t aoff = s ? OFF_A1 : OFF_A0;
        const uint32_t boff = s ? OFF_B1 : OFF_B0;
        if (kt + 1 < nk) {                 // prefetch next chunk into back buffer
            prefB(kt + 1, s ? OFF_B0 : OFF_B1);
            scores(kt + 1, s ? OFF_A0 : OFF_A1);
        }
        const char* Ab = sm + aoff;
        const char* Bb = sm + boff;
#pragma unroll
        for (int kf = 0; kf < 4; ++kf) {
            const int kb = (8 * kf + 2 * t) * 4;
            uint32_t a[2][4];
#pragma unroll
            for (int mf = 0; mf < 2; ++mf) {
                const int r0 = wm * 32 + mf * 16 + g;
                const float2 v0 = *(const float2*)(Ab + SW128_(r0 * 128 + kb));
                const float2 v1 = *(const float2*)(Ab + SW128_((r0 + 8) * 128 + kb));
                a[mf][0] = __float_as_uint(v0.x); a[mf][2] = __float_as_uint(v0.y);
                a[mf][1] = __float_as_uint(v1.x); a[mf][3] = __float_as_uint(v1.y);
            }
#pragma unroll
            for (int nf = 0; nf < 8; ++nf) {
                const int n = wn * 64 + nf * 8 + g;
                const float2 bv = *(const float2*)(Bb + SW128_(n * 128 + kb));
                const uint32_t b0 = __float_as_uint(bv.x), b1 = __float_as_uint(bv.y);
                mma8_(acc[0][nf], a[0][0], a[0][1], a[0][2], a[0][3], b0, b1);
                mma8_(acc[1][nf], a[1][0], a[1][1], a[1][2], a[1][3], b0, b1);
            }
        }
        CPA_WAIT0_;
        __syncthreads();
    }

    // LN epilogue: per-row sum/sumsq partials (quad reduce -> smem -> combine)
#pragma unroll
    for (int mf = 0; mf < 2; ++mf)
#pragma unroll
        for (int h = 0; h < 2; ++h) {
            float s = 0.f, q2 = 0.f;
#pragma unroll
            for (int nf = 0; nf < 8; ++nf) {
                const float v0 = acc[mf][nf][2 * h], v1 = acc[mf][nf][2 * h + 1];
                s += v0 + v1;
                q2 = fmaf(v0, v0, fmaf(v1, v1, q2));
            }
            s  += __shfl_xor_sync(0xffffffffu, s, 1);
            s  += __shfl_xor_sync(0xffffffffu, s, 2);
            q2 += __shfl_xor_sync(0xffffffffu, q2, 1);
            q2 += __shfl_xor_sync(0xffffffffu, q2, 2);
            if (t == 0) {
                const int r = wm * 32 + mf * 16 + h * 8 + g;
                ps[r * 4 + wn] = s; pq[r * 4 + wn] = q2;
            }
        }
    __syncthreads();

#pragma unroll
    for (int mf = 0; mf < 2; ++mf)
#pragma unroll
        for (int h = 0; h < 2; ++h) {
            const int r = wm * 32 + mf * 16 + h * 8 + g;
            const float su = ps[r * 4] + ps[r * 4 + 1] + ps[r * 4 + 2] + ps[r * 4 + 3];
            const float sq = pq[r * 4] + pq[r * 4 + 1] + pq[r * 4 + 2] + pq[r * 4 + 3];
            const float mu  = su * (1.f / 256.f);
            const float var = fmaxf(sq * (1.f / 256.f) - mu * mu, 0.f);
            const float rs  = rsqrtf(var + 1e-6f);
            float* dst = g_hidden + (size_t)(b * L_ + i0 + r) * 256;
#pragma unroll
            for (int nf = 0; nf < 8; ++nf)
#pragma unroll
                for (int e = 0; e < 2; ++e) {
                    const int c = wn * 64 + nf * 8 + 2 * t + e;
                    const float o = (acc[mf][nf][2 * h + e] - mu) * rs * gsm[c] + bsm[c];
                    dst[kperm_(c)] = __uint_as_float(tf32r_(o));  // k-interleaved for k3
                }
        }
}

// ---------------------------------------------------------------------------
// k3: out = softplus( w_time . relu([noise|hidden] @ [Wn;Wi]^T) + b ) — pipelined
// ---------------------------------------------------------------------------
__global__ __launch_bounds__(512) void k3_mma(
    const float* __restrict__ wt, const float* __restrict__ btime,
    float* __restrict__ out)
{
    extern __shared__ char sm[];
    const uint32_t sbase = s2u_(sm);
    float* wsm = (float*)(sm + OFF_PRM);
    float* pp  = (float*)sm;   // alias A0 after mainloop

    const int tid = threadIdx.x, lane = tid & 31, warp = tid >> 5;
    const int g = lane >> 2, t = lane & 3, wm = warp >> 2, wn = warp & 3;
    if (tid < 256) wsm[tid] = wt[tid];

    const int b  = blockIdx.y;
    const int i0 = blockIdx.x * 128;

    const int bn_ = tid >> 3, bj4 = (tid & 7) * 4;      // B-tile thread mapping
    const int ai_ = tid >> 3;                           // A-tile (same shape, 2 iters)

    auto pref = [&](int kt, uint32_t aoff, uint32_t boff) {
        const int kc = kt * 32;
#pragma unroll
        for (int q = 0; q < 4; ++q) {
            const int n = bn_ + 64 * q;
            cpa16_(sbase + boff + SW128_(n * 128 + bj4 * 4), g_Wp + n * 512 + kc + bj4);
        }
        const float* Xs = (kt < 8) ? (g_noiseP + (size_t)(b * L_ + i0) * 256 + kc)
                                   : (g_hidden + (size_t)(b * L_ + i0) * 256 + (kc - 256));
#pragma unroll
        for (int q = 0; q < 2; ++q) {
            const int i_ = ai_ + 64 * q;
            cpa16_(sbase + aoff + SW128_(i_ * 128 + bj4 * 4), Xs + (size_t)i_ * 256 + bj4);
        }
        CPA_COMMIT_;
    };

    float acc[2][8][4];
#pragma unroll
    for (int mf = 0; mf < 2; ++mf)
#pragma unroll
        for (int nf = 0; nf < 8; ++nf)
#pragma unroll
            for (int e = 0; e < 4; ++e) acc[mf][nf][e] = 0.f;

    pref(0, OFF_A0, OFF_B0);
    CPA_WAIT0_;
    __syncthreads();

    for (int kt = 0; kt < 16; ++kt) {
        const int s = kt & 1;
        const uint32_t aoff = s ? OFF_A1 : OFF_A0;
        const uint32_t boff = s ? OFF_B1 : OFF_B0;
        if (kt < 15) pref(kt + 1, s ? OFF_A0 : OFF_A1, s ? OFF_B0 : OFF_B1);
        const char* Ab = sm + aoff;
        const char* Bb = sm + boff;
#pragma unroll
        for (int kf = 0; kf < 4; ++kf) {
            const int kb = (8 * kf + 2 * t) * 4;
            uint32_t a[2][4];
#pragma unroll
            for (int mf = 0; mf < 2; ++mf) {
                const int r0 = wm * 32 + mf * 16 + g;
                const float2 v0 = *(const float2*)(Ab + SW128_(r0 * 128 + kb));
                const float2 v1 = *(const float2*)(Ab + SW128_((r0 + 8) * 128 + kb));
                a[mf][0] = __float_as_uint(v0.x); a[mf][2] = __float_as_uint(v0.y);
                a[mf][1] = __float_as_uint(v1.x); a[mf][3] = __float_as_uint(v1.y);
            }
#pragma unroll
            for (int nf = 0; nf < 8; ++nf) {
                const int n = wn * 64 + nf * 8 + g;
                const float2 bv = *(const float2*)(Bb + SW128_(n * 128 + kb));
                const uint32_t b0 = __float_as_uint(bv.x), b1 = __float_as_uint(bv.y);
                mma8_(acc[0][nf], a[0][0], a[0][1], a[0][2], a[0][3], b0, b1);
                mma8_(acc[1][nf], a[1][0], a[1][1], a[1][2], a[1][3], b0, b1);
            }
        }
        CPA_WAIT0_;
        __syncthreads();
    }

    // epilogue: relu + dot(w_time) partials -> quad reduce -> smem -> softplus
#pragma unroll
    for (int mf = 0; mf < 2; ++mf)
#pragma unroll
        for (int h = 0; h < 2; ++h) {
            float p = 0.f;
#pragma unroll
            for (int nf = 0; nf < 8; ++nf)
#pragma unroll
                for (int e = 0; e < 2; ++e) {
                    const int c = wn * 64 + nf * 8 + 2 * t + e;
                    p = fmaf(wsm[c], fmaxf(acc[mf][nf][2 * h + e], 0.f), p);
                }
            p += __shfl_xor_sync(0xffffffffu, p, 1);
            p += __shfl_xor_sync(0xffffffffu, p, 2);
            if (t == 0) pp[(wm * 32 + mf * 16 + h * 8 + g) * 4 + wn] = p;
        }
    __syncthreads();
    if (tid < 128) {
        const float s = pp[tid * 4] + pp[tid * 4 + 1] + pp[tid * 4 + 2] + pp[tid * 4 + 3];
        out[b * L_ + i0 + tid] = softplusf_(s + btime[0]);
    }
}

// ---------------------------------------------------------------------------
// Input order: 0 event_type (unused), 1 event_time, 2 noise, 3 gate_params,
// 4 length_scale, 5 Wn, 6 Wi, 7 w_time, 8 b_time, 9 ln_gamma, 10 ln_beta.
// ---------------------------------------------------------------------------
extern "C" void kernel_launch(void* const* d_in, const int* in_sizes, int n_in,
                              void* d_out, int out_size) {
    const float* et    = (const float*)d_in[1];
    const float* noise = (const float*)d_in[2];
    const float* gp    = (const float*)d_in[3];
    const float* lsc   = (const float*)d_in[4];
    const float* Wn    = (const float*)d_in[5];
    const float* Wi    = (const float*)d_in[6];
    const float* wt    = (const float*)d_in[7];
    const float* bt    = (const float*)d_in[8];
    const float* gam   = (const float*)d_in[9];
    const float* bet   = (const float*)d_in[10];
    float* out = (float*)d_out;

    cudaFuncSetAttribute(k2_mma, cudaFuncAttributeMaxDynamicSharedMemorySize, SM_TOT);
    cudaFuncSetAttribute(k3_mma, cudaFuncAttributeMaxDynamicSharedMemorySize, SM_TOT);

    embT_kernel<<<(B_ * D_ * L_) / 256, 256>>>(et);
    np_kernel<<<(B_ * L_ * D_) / 256, 256>>>(noise);
    wp_kernel<<<(256 * 512) / 256, 256>>>(Wn, Wi);
    k2_mma<<<dim3(L_ / 128, B_), 512, SM_TOT>>>(et, gp, lsc, gam, bet);
    k3_mma<<<dim3(L_ / 128, B_), 512, SM_TOT>>>(wt, bt, out);
}

// round 9
// speedup vs baseline: 5.9853x; 2.4247x over previous
#include <cuda_runtime.h>
#include <cuda_fp16.h>
#include <math.h>
#include <stdint.h>

#define B_ 16
#define L_ 2048
#define D_ 256

// Scratch (static device arrays — no allocation allowed)
__device__ __align__(16) __half g_scoreH[(size_t)B_ * L_ * L_];   // [b][i][j-perm], tril(+zero superdiag)
__device__ __align__(16) __half g_embTH[(size_t)B_ * D_ * L_];    // [b][d][j-perm]
__device__ __align__(16) __half g_hiddenH[(size_t)B_ * L_ * D_];  // [b][i][k-perm]
__device__ __align__(16) __half g_noiseH[(size_t)B_ * L_ * D_];   // [b][i][k-perm]
__device__ __align__(16) __half g_WpH[512 * 256];                 // [n][k=512 perm]

// ---------------------------------------------------------------------------
// helpers
// ---------------------------------------------------------------------------
__device__ __forceinline__ float softplusf_(float x) {
    return fmaxf(x, 0.f) + log1pf(__expf(-fabsf(x)));
}
__device__ __forceinline__ float sigmoidf_(float x) {
    return 1.f / (1.f + __expf(-x));
}
__device__ __forceinline__ uint32_t h2_(float lo, float hi) {
    __half2 h = __floats2half2_rn(lo, hi);
    return *(uint32_t*)&h;
}
__device__ __forceinline__ uint32_t s2u_(const void* p) {
    uint32_t a;
    asm("{ .reg .u64 t; cvta.to.shared.u64 t, %1; cvt.u32.u64 %0, t; }" : "=r"(a) : "l"(p));
    return a;
}
__device__ __forceinline__ void cpa16_(uint32_t dst, const void* src) {
    asm volatile("cp.async.cg.shared.global [%0], [%1], 16;" :: "r"(dst), "l"(src) : "memory");
}
#define CPA_COMMIT_ asm volatile("cp.async.commit_group;" ::: "memory")
#define CPA_WAIT0_  asm volatile("cp.async.wait_group 0;" ::: "memory")

__device__ __forceinline__ void mma16_(float* c, uint32_t a0, uint32_t a1, uint32_t a2,
                                       uint32_t a3, uint32_t b0, uint32_t b1) {
    asm volatile(
        "mma.sync.aligned.m16n8k16.row.col.f32.f16.f16.f32 "
        "{%0,%1,%2,%3}, {%4,%5,%6,%7}, {%8,%9}, {%0,%1,%2,%3};"
        : "+f"(c[0]), "+f"(c[1]), "+f"(c[2]), "+f"(c[3])
        : "r"(a0), "r"(a1), "r"(a2), "r"(a3), "r"(b0), "r"(b1));
}

// Pair-perm within each 64-half K block: logical pair p (0..31) -> phys (p&3)*8 + (p>>2).
// Inverse (phys l -> logical p): (l&7)*4 + (l>>3).

// smem: A 2x16KB | B 2x32KB | params 2KB
#define KOFF_A0  0
#define KOFF_A1  16384
#define KOFF_B0  32768
#define KOFF_B1  65536
#define KOFF_PRM 98304
#define KSM_TOT  100352

// ---------------------------------------------------------------------------
// prep 1: scores -> g_scoreH (lower-triangle 64x64 tiles + zeroed superdiag tiles)
// ---------------------------------------------------------------------------
__global__ __launch_bounds__(256) void score_kernel(
    const float* __restrict__ et, const float* __restrict__ gp,
    const float* __restrict__ lsc)
{
    __shared__ float ei[64], ej[64];
    __shared__ uint32_t sct[64 * 33];

    const int tt = blockIdx.x, b = blockIdx.y;
    int it = (int)((sqrtf(8.f * (float)tt + 1.f) - 1.f) * 0.5f);
    while ((it + 1) * (it + 2) / 2 <= tt) ++it;
    while (it * (it + 1) / 2 > tt) --it;
    const int jt = tt - it * (it + 1) / 2;

    const int tid = threadIdx.x;
    if (tid < 64) ei[tid] = __ldg(&et[b * L_ + it * 64 + tid]);
    else if (tid < 128) ej[tid - 64] = __ldg(&et[b * L_ + jt * 64 + (tid - 64)]);

    const float ls      = softplusf_(lsc[0]);
    const float inv_ls2 = 1.f / (ls * ls);
    const float inv_s   = 1.f / sigmoidf_(gp[1]);
    const float c1      = inv_s * 0.005f;
    const float c0      = -sigmoidf_(gp[0]) * inv_s;
    __syncthreads();

    const int il = tid >> 2, jseg = (tid & 3) * 16;
    const float ti = ei[il];
    const int ig = it * 64 + il;
#pragma unroll
    for (int q = 0; q < 16; q += 2) {
        float sv[2];
#pragma unroll
        for (int e = 0; e < 2; ++e) {
            const int jl = jseg + q + e;
            const float dd = fabsf(ti - ej[jl]);
            const float kv = __expf(-dd * dd * inv_ls2);
            float th;
            asm("tanh.approx.f32 %0, %1;" : "=f"(th) : "f"(fmaf(dd, c1, c0)));
            float s = fmaf(kv, th, kv);
            if (jt * 64 + jl > ig) s = 0.f;   // causal (keep diagonal)
            sv[e] = s;
        }
        sct[il * 33 + (jseg + q) / 2] = h2_(sv[0], sv[1]);
    }
    __syncthreads();

    const int w = tid >> 5, l = tid & 31;
    const int p = (l & 7) * 4 + (l >> 3);   // inverse pair-perm
    char* base = (char*)g_scoreH + ((size_t)(b * L_ + it * 64) * L_ + jt * 64) * 2;
#pragma unroll
    for (int rr = 0; rr < 8; ++rr) {
        const int r = w * 8 + rr;
        *(uint32_t*)(base + (size_t)r * (L_ * 2) + l * 4) = sct[r * 33 + p];
    }
    if (it == jt && it < 31) {   // zero the tile right of the diagonal
        char* zb = (char*)g_scoreH + ((size_t)(b * L_ + it * 64) * L_ + (jt + 1) * 64) * 2;
#pragma unroll
        for (int rr = 0; rr < 8; ++rr) {
            const int r = w * 8 + rr;
            *(uint32_t*)(zb + (size_t)r * (L_ * 2) + l * 4) = 0u;
        }
    }
}

// ---------------------------------------------------------------------------
// prep 2: emb^T (half, pair-permuted along j)
// ---------------------------------------------------------------------------
__global__ void embTH_kernel(const float* __restrict__ et) {
    const int idx = blockIdx.x * 256 + threadIdx.x;   // B*D*L/2 pair-slots
    const int l = idx & 31, blk = (idx >> 5) & 31, d = (idx >> 10) & 255, b = idx >> 18;
    const int p = (l & 7) * 4 + (l >> 3);
    const int j = blk * 64 + 2 * p;
    const float f = exp2f(-0.10381025296522991f * (float)d);
    const float a0 = __ldg(&et[b * L_ + j]) * f;
    const float a1 = __ldg(&et[b * L_ + j + 1]) * f;
    const float v0 = (d & 1) ? cosf(a0) : sinf(a0);
    const float v1 = (d & 1) ? cosf(a1) : sinf(a1);
    *(uint32_t*)((char*)g_embTH + ((size_t)(b * 256 + d) * L_ + blk * 64) * 2 + l * 4) = h2_(v0, v1);
}

// prep 3: noise (half, pair-permuted along k)
__global__ void noiseH_kernel(const float* __restrict__ noise) {
    const int idx = blockIdx.x * 256 + threadIdx.x;   // B*L*D/2
    const int l = idx & 31, blk = (idx >> 5) & 3, row = idx >> 7;
    const int p = (l & 7) * 4 + (l >> 3);
    const int k = blk * 64 + 2 * p;
    const float v0 = __ldg(&noise[(size_t)row * 256 + k]);
    const float v1 = __ldg(&noise[(size_t)row * 256 + k + 1]);
    *(uint32_t*)((char*)g_noiseH + (size_t)row * 512 + blk * 128 + l * 4) = h2_(v0, v1);
}

// prep 4: W = [Wn | Wi] rows (half, pair-permuted along k)
__global__ void wpH_kernel(const float* __restrict__ Wn, const float* __restrict__ Wi) {
    const int idx = blockIdx.x * 256 + threadIdx.x;   // 256*512/2
    const int l = idx & 31, blk = (idx >> 5) & 7, n = idx >> 8;
    const int p = (l & 7) * 4 + (l >> 3);
    const int k = blk * 64 + 2 * p;
    const float v0 = (k < 256) ? __ldg(&Wn[n * 256 + k]) : __ldg(&Wi[n * 256 + k - 256]);
    const float v1 = (k + 1 < 256) ? __ldg(&Wn[n * 256 + k + 1]) : __ldg(&Wi[n * 256 + k + 1 - 256]);
    *(uint32_t*)((char*)g_WpH + (size_t)n * 1024 + blk * 128 + l * 4) = h2_(v0, v1);
}

// ---------------------------------------------------------------------------
// k2: hidden = LN( tril(S) @ E ) — fp16 mma, pure GEMM, balanced tile-pairs
// CTA handles i-tiles {15-bx, bx}: constant 34 K-chunks total.
// ---------------------------------------------------------------------------
__global__ __launch_bounds__(512) void k2_mma(
    const float* __restrict__ gamma, const float* __restrict__ beta)
{
    extern __shared__ char sm[];
    const uint32_t sb = s2u_(sm);
    float* gsm = (float*)(sm + KOFF_PRM);
    float* bsm = gsm + 256;
    float* ps  = (float*)sm;      // alias A0 (only used at epilogue)
    float* pq  = ps + 512;

    const int tid = threadIdx.x, lane = tid & 31, warp = tid >> 5;
    const int g = lane >> 2, t = lane & 3, wm = warp >> 2, wn = warp & 3;
    if (tid < 256) { gsm[tid] = gamma[tid]; bsm[tid] = beta[tid]; }

    const int b = blockIdx.y;
    const char* Bbase = (const char*)g_embTH + (size_t)b * D_ * L_ * 2;

    for (int ph = 0; ph < 2; ++ph) {
        const int ib = ph == 0 ? 15 - (int)blockIdx.x : (int)blockIdx.x;
        const int i0 = ib * 128;
        const int nk = 2 * (ib + 1);
        const char* Abase = (const char*)g_scoreH + (size_t)(b * L_ + i0) * L_ * 2;

        auto pref = [&](int kt, uint32_t ao, uint32_t bo) {
            const int j0b = kt * 128;   // byte offset of chunk within row
#pragma unroll
            for (int q = 0; q < 2; ++q) {
                const int c = tid + 512 * q;
                const int r = c >> 3, u = (c & 7) * 16;
                cpa16_(sb + ao + r * 128 + (u ^ ((r & 7) << 4)),
                       Abase + (size_t)r * (L_ * 2) + j0b + u);
            }
#pragma unroll
            for (int q = 0; q < 4; ++q) {
                const int c = tid + 512 * q;
                const int n = c >> 3, u = (c & 7) * 16;
                cpa16_(sb + bo + n * 128 + (u ^ ((n & 7) << 4)),
                       Bbase + (size_t)n * (L_ * 2) + j0b + u);
            }
            CPA_COMMIT_;
        };

        float acc[2][8][4];
#pragma unroll
        for (int mf = 0; mf < 2; ++mf)
#pragma unroll
            for (int nf = 0; nf < 8; ++nf)
#pragma unroll
                for (int e = 0; e < 4; ++e) acc[mf][nf][e] = 0.f;

        __syncthreads();               // params ready / ps-pq alias released
        pref(0, KOFF_A0, KOFF_B0);
        CPA_WAIT0_;
        __syncthreads();

        for (int kt = 0; kt < nk; ++kt) {
            const int s = kt & 1;
            const uint32_t ao = s ? KOFF_A1 : KOFF_A0;
            const uint32_t bo = s ? KOFF_B1 : KOFF_B0;
            if (kt + 1 < nk) pref(kt + 1, s ? KOFF_A0 : KOFF_A1, s ? KOFF_B0 : KOFF_B1);
            const char* Ab = sm + ao;
            const char* Bb = sm + bo;
#pragma unroll
            for (int s2 = 0; s2 < 2; ++s2) {
                const int toff = t * 32 + s2 * 16;
                uint4 ar[2][2];
#pragma unroll
                for (int mf = 0; mf < 2; ++mf) {
                    const int r0 = wm * 32 + mf * 16 + g;
                    ar[mf][0] = *(const uint4*)(Ab + r0 * 128 + (toff ^ ((r0 & 7) << 4)));
                    const int r1 = r0 + 8;
                    ar[mf][1] = *(const uint4*)(Ab + r1 * 128 + (toff ^ ((r1 & 7) << 4)));
                }
#pragma unroll
                for (int nf = 0; nf < 8; ++nf) {
                    const int n = wn * 64 + nf * 8 + g;
                    const uint4 br = *(const uint4*)(Bb + n * 128 + (toff ^ ((n & 7) << 4)));
                    mma16_(acc[0][nf], ar[0][0].x, ar[0][1].x, ar[0][0].y, ar[0][1].y, br.x, br.y);
                    mma16_(acc[1][nf], ar[1][0].x, ar[1][1].x, ar[1][0].y, ar[1][1].y, br.x, br.y);
                    mma16_(acc[0][nf], ar[0][0].z, ar[0][1].z, ar[0][0].w, ar[0][1].w, br.z, br.w);
                    mma16_(acc[1][nf], ar[1][0].z, ar[1][1].z, ar[1][0].w, ar[1][1].w, br.z, br.w);
                }
            }
            CPA_WAIT0_;
            __syncthreads();
        }

        // LN epilogue
#pragma unroll
        for (int mf = 0; mf < 2; ++mf)
#pragma unroll
            for (int h = 0; h < 2; ++h) {
                float s = 0.f, q2 = 0.f;
#pragma unroll
                for (int nf = 0; nf < 8; ++nf) {
                    const float v0 = acc[mf][nf][2 * h], v1 = acc[mf][nf][2 * h + 1];
                    s += v0 + v1;
                    q2 = fmaf(v0, v0, fmaf(v1, v1, q2));
                }
                s  += __shfl_xor_sync(0xffffffffu, s, 1);
                s  += __shfl_xor_sync(0xffffffffu, s, 2);
                q2 += __shfl_xor_sync(0xffffffffu, q2, 1);
                q2 += __shfl_xor_sync(0xffffffffu, q2, 2);
                if (t == 0) {
                    const int r = wm * 32 + mf * 16 + h * 8 + g;
                    ps[r * 4 + wn] = s; pq[r * 4 + wn] = q2;
                }
            }
        __syncthreads();

#pragma unroll
        for (int mf = 0; mf < 2; ++mf)
#pragma unroll
            for (int h = 0; h < 2; ++h) {
                const int r = wm * 32 + mf * 16 + h * 8 + g;
                const float su = ps[r * 4] + ps[r * 4 + 1] + ps[r * 4 + 2] + ps[r * 4 + 3];
                const float sq = pq[r * 4] + pq[r * 4 + 1] + pq[r * 4 + 2] + pq[r * 4 + 3];
                const float mu  = su * (1.f / 256.f);
                const float var = fmaxf(sq * (1.f / 256.f) - mu * mu, 0.f);
                const float rs  = rsqrtf(var + 1e-6f);
                char* dst = (char*)g_hiddenH + (size_t)(b * L_ + i0 + r) * 512;
#pragma unroll
                for (int nf = 0; nf < 8; ++nf) {
                    const int c = wn * 64 + nf * 8 + 2 * t;
                    const float o0 = (acc[mf][nf][2 * h + 0] - mu) * rs * gsm[c] + bsm[c];
                    const float o1 = (acc[mf][nf][2 * h + 1] - mu) * rs * gsm[c + 1] + bsm[c + 1];
                    const int p = (c & 63) >> 1;
                    const int pp = (p & 3) * 8 + (p >> 2);
                    *(uint32_t*)(dst + (c >> 6) * 128 + pp * 4) = h2_(o0, o1);
                }
            }
    }
}

// ---------------------------------------------------------------------------
// k3: out = softplus( w_time . relu([noise|hidden] @ [Wn;Wi]^T) + b )
// ---------------------------------------------------------------------------
__global__ __launch_bounds__(512) void k3_mma(
    const float* __restrict__ wt, const float* __restrict__ btime,
    float* __restrict__ out)
{
    extern __shared__ char sm[];
    const uint32_t sb = s2u_(sm);
    float* wsm = (float*)(sm + KOFF_PRM);
    float* pp  = (float*)sm;   // alias A0 after mainloop

    const int tid = threadIdx.x, lane = tid & 31, warp = tid >> 5;
    const int g = lane >> 2, t = lane & 3, wm = warp >> 2, wn = warp & 3;
    if (tid < 256) wsm[tid] = wt[tid];

    const int b  = blockIdx.y;
    const int i0 = blockIdx.x * 128;

    auto pref = [&](int kt, uint32_t ao, uint32_t bo) {
        const char* Asrc = (kt < 4)
            ? (const char*)g_noiseH + (size_t)(b * L_ + i0) * 512 + kt * 128
            : (const char*)g_hiddenH + (size_t)(b * L_ + i0) * 512 + (kt - 4) * 128;
#pragma unroll
        for (int q = 0; q < 2; ++q) {
            const int c = tid + 512 * q;
            const int r = c >> 3, u = (c & 7) * 16;
            cpa16_(sb + ao + r * 128 + (u ^ ((r & 7) << 4)), Asrc + (size_t)r * 512 + u);
        }
#pragma unroll
        for (int q = 0; q < 4; ++q) {
            const int c = tid + 512 * q;
            const int n = c >> 3, u = (c & 7) * 16;
            cpa16_(sb + bo + n * 128 + (u ^ ((n & 7) << 4)),
                   (const char*)g_WpH + (size_t)n * 1024 + kt * 128 + u);
        }
        CPA_COMMIT_;
    };

    float acc[2][8][4];
#pragma unroll
    for (int mf = 0; mf < 2; ++mf)
#pragma unroll
        for (int nf = 0; nf < 8; ++nf)
#pragma unroll
            for (int e = 0; e < 4; ++e) acc[mf][nf][e] = 0.f;

    __syncthreads();
    pref(0, KOFF_A0, KOFF_B0);
    CPA_WAIT0_;
    __syncthreads();

    for (int kt = 0; kt < 8; ++kt) {
        const int s = kt & 1;
        const uint32_t ao = s ? KOFF_A1 : KOFF_A0;
        const uint32_t bo = s ? KOFF_B1 : KOFF_B0;
        if (kt < 7) pref(kt + 1, s ? KOFF_A0 : KOFF_A1, s ? KOFF_B0 : KOFF_B1);
        const char* Ab = sm + ao;
        const char* Bb = sm + bo;
#pragma unroll
        for (int s2 = 0; s2 < 2; ++s2) {
            const int toff = t * 32 + s2 * 16;
            uint4 ar[2][2];
#pragma unroll
            for (int mf = 0; mf < 2; ++mf) {
                const int r0 = wm * 32 + mf * 16 + g;
                ar[mf][0] = *(const uint4*)(Ab + r0 * 128 + (toff ^ ((r0 & 7) << 4)));
                const int r1 = r0 + 8;
                ar[mf][1] = *(const uint4*)(Ab + r1 * 128 + (toff ^ ((r1 & 7) << 4)));
            }
#pragma unroll
            for (int nf = 0; nf < 8; ++nf) {
                const int n = wn * 64 + nf * 8 + g;
                const uint4 br = *(const uint4*)(Bb + n * 128 + (toff ^ ((n & 7) << 4)));
                mma16_(acc[0][nf], ar[0][0].x, ar[0][1].x, ar[0][0].y, ar[0][1].y, br.x, br.y);
                mma16_(acc[1][nf], ar[1][0].x, ar[1][1].x, ar[1][0].y, ar[1][1].y, br.x, br.y);
                mma16_(acc[0][nf], ar[0][0].z, ar[0][1].z, ar[0][0].w, ar[0][1].w, br.z, br.w);
                mma16_(acc[1][nf], ar[1][0].z, ar[1][1].z, ar[1][0].w, ar[1][1].w, br.z, br.w);
            }
        }
        CPA_WAIT0_;
        __syncthreads();
    }

    // epilogue: relu + dot(w_time) partials -> quad reduce -> smem -> softplus
#pragma unroll
    for (int mf = 0; mf < 2; ++mf)
#pragma unroll
        for (int h = 0; h < 2; ++h) {
            float p = 0.f;
#pragma unroll
            for (int nf = 0; nf < 8; ++nf)
#pragma unroll
                for (int e = 0; e < 2; ++e) {
                    const int c = wn * 64 + nf * 8 + 2 * t + e;
                    p = fmaf(wsm[c], fmaxf(acc[mf][nf][2 * h + e], 0.f), p);
                }
            p += __shfl_xor_sync(0xffffffffu, p, 1);
            p += __shfl_xor_sync(0xffffffffu, p, 2);
            if (t == 0) pp[(wm * 32 + mf * 16 + h * 8 + g) * 4 + wn] = p;
        }
    __syncthreads();
    if (tid < 128) {
        const float s = pp[tid * 4] + pp[tid * 4 + 1] + pp[tid * 4 + 2] + pp[tid * 4 + 3];
        out[b * L_ + i0 + tid] = softplusf_(s + btime[0]);
    }
}

// ---------------------------------------------------------------------------
// Input order: 0 event_type (unused), 1 event_time, 2 noise, 3 gate_params,
// 4 length_scale, 5 Wn, 6 Wi, 7 w_time, 8 b_time, 9 ln_gamma, 10 ln_beta.
// ---------------------------------------------------------------------------
extern "C" void kernel_launch(void* const* d_in, const int* in_sizes, int n_in,
                              void* d_out, int out_size) {
    const float* et    = (const float*)d_in[1];
    const float* noise = (const float*)d_in[2];
    const float* gp    = (const float*)d_in[3];
    const float* lsc   = (const float*)d_in[4];
    const float* Wn    = (const float*)d_in[5];
    const float* Wi    = (const float*)d_in[6];
    const float* wt    = (const float*)d_in[7];
    const float* bt    = (const float*)d_in[8];
    const float* gam   = (const float*)d_in[9];
    const float* bet   = (const float*)d_in[10];
    float* out = (float*)d_out;

    cudaFuncSetAttribute(k2_mma, cudaFuncAttributeMaxDynamicSharedMemorySize, KSM_TOT);
    cudaFuncSetAttribute(k3_mma, cudaFuncAttributeMaxDynamicSharedMemorySize, KSM_TOT);

    score_kernel<<<dim3(528, B_), 256>>>(et, gp, lsc);
    embTH_kernel<<<(B_ * D_ * L_ / 2) / 256, 256>>>(et);
    noiseH_kernel<<<(B_ * L_ * D_ / 2) / 256, 256>>>(noise);
    wpH_kernel<<<(256 * 512 / 2) / 256, 256>>>(Wn, Wi);
    k2_mma<<<dim3(8, B_), 512, KSM_TOT>>>(gam, bet);
    k3_mma<<<dim3(16, B_), 512, KSM_TOT>>>(wt, bt, out);
}

// round 12
// speedup vs baseline: 6.1422x; 1.0262x over previous
#include <cuda_runtime.h>
#include <cuda_fp16.h>
#include <math.h>
#include <stdint.h>

#define B_ 16
#define L_ 2048
#define D_ 256

// Scratch (static device arrays — no allocation allowed)
__device__ __align__(16) __half g_scoreH[(size_t)B_ * L_ * L_];   // [b][i][j-perm], tril(+zero superdiag)
__device__ __align__(16) __half g_embTH[(size_t)B_ * D_ * L_];    // [b][d][j-perm]
__device__ __align__(16) __half g_hiddenH[(size_t)B_ * L_ * D_];  // [b][i][k-perm]
__device__ __align__(16) __half g_noiseH[(size_t)B_ * L_ * D_];   // [b][i][k-perm]
__device__ __align__(16) __half g_WpH[512 * 256];                 // [n][k=512 perm]

// ---------------------------------------------------------------------------
// helpers
// ---------------------------------------------------------------------------
__device__ __forceinline__ float softplusf_(float x) {
    return fmaxf(x, 0.f) + log1pf(__expf(-fabsf(x)));
}
__device__ __forceinline__ float sigmoidf_(float x) {
    return 1.f / (1.f + __expf(-x));
}
__device__ __forceinline__ uint32_t h2_(float lo, float hi) {
    __half2 h = __floats2half2_rn(lo, hi);
    return *(uint32_t*)&h;
}
__device__ __forceinline__ uint32_t s2u_(const void* p) {
    uint32_t a;
    asm("{ .reg .u64 t; cvta.to.shared.u64 t, %1; cvt.u32.u64 %0, t; }" : "=r"(a) : "l"(p));
    return a;
}
__device__ __forceinline__ void cpa16_(uint32_t dst, const void* src) {
    asm volatile("cp.async.cg.shared.global [%0], [%1], 16;" :: "r"(dst), "l"(src) : "memory");
}
#define CPA_COMMIT_ asm volatile("cp.async.commit_group;" ::: "memory")
#define CPA_WAIT0_  asm volatile("cp.async.wait_group 0;" ::: "memory")

__device__ __forceinline__ void mma16_(float* c, uint32_t a0, uint32_t a1, uint32_t a2,
                                       uint32_t a3, uint32_t b0, uint32_t b1) {
    asm volatile(
        "mma.sync.aligned.m16n8k16.row.col.f32.f16.f16.f32 "
        "{%0,%1,%2,%3}, {%4,%5,%6,%7}, {%8,%9}, {%0,%1,%2,%3};"
        : "+f"(c[0]), "+f"(c[1]), "+f"(c[2]), "+f"(c[3])
        : "r"(a0), "r"(a1), "r"(a2), "r"(a3), "r"(b0), "r"(b1));
}

// K=128 chunks, each = two 64-k sub-tiles with the proven XOR-16 swizzle layout.
// smem: A 2x32KB | B 2x64KB | params 2KB  (192KB stages + 2KB)
#define KOFF_A0  0
#define KOFF_A1  32768
#define KOFF_B0  65536
#define KOFF_B1  131072
#define KOFF_PRM 196608
#define KSM_TOT  198656

// ---------------------------------------------------------------------------
// fused prep kernel: all independent prep work in one launch.
// sections (blockIdx.x ranges): scores | embTH | noiseH | wpH
// ---------------------------------------------------------------------------
#define NB_SCORE (528 * B_)                       // 8448
#define NB_EMB   ((B_ * D_ * L_ / 2) / 256)       // 16384
#define NB_NOISE ((B_ * L_ * D_ / 2) / 256)       // 16384
#define NB_WP    ((256 * 512 / 2) / 256)          // 256
#define NB_TOT   (NB_SCORE + NB_EMB + NB_NOISE + NB_WP)

__global__ __launch_bounds__(256) void prep_kernel(
    const float* __restrict__ et, const float* __restrict__ gp,
    const float* __restrict__ lsc, const float* __restrict__ noise,
    const float* __restrict__ Wn, const float* __restrict__ Wi)
{
    const int bid = blockIdx.x;
    const int tid = threadIdx.x;

    if (bid < NB_SCORE) {
        // ---- scores: lower-triangle 64x64 tiles (+zero superdiag tiles) ----
        __shared__ float ei[64], ej[64];
        __shared__ uint32_t sct[64 * 33];

        const int b = bid / 528, tt = bid % 528;
        int it = (int)((sqrtf(8.f * (float)tt + 1.f) - 1.f) * 0.5f);
        while ((it + 1) * (it + 2) / 2 <= tt) ++it;
        while (it * (it + 1) / 2 > tt) --it;
        const int jt = tt - it * (it + 1) / 2;

        if (tid < 64) ei[tid] = __ldg(&et[b * L_ + it * 64 + tid]);
        else if (tid < 128) ej[tid - 64] = __ldg(&et[b * L_ + jt * 64 + (tid - 64)]);

        const float ls      = softplusf_(lsc[0]);
        const float inv_ls2 = 1.f / (ls * ls);
        const float inv_s   = 1.f / sigmoidf_(gp[1]);
        const float c1      = inv_s * 0.005f;
        const float c0      = -sigmoidf_(gp[0]) * inv_s;
        __syncthreads();

        const int il = tid >> 2, jseg = (tid & 3) * 16;
        const float ti = ei[il];
        const int ig = it * 64 + il;
#pragma unroll
        for (int q = 0; q < 16; q += 2) {
            float sv[2];
#pragma unroll
            for (int e = 0; e < 2; ++e) {
                const int jl = jseg + q + e;
                const float dd = fabsf(ti - ej[jl]);
                const float kv = __expf(-dd * dd * inv_ls2);
                float th;
                asm("tanh.approx.f32 %0, %1;" : "=f"(th) : "f"(fmaf(dd, c1, c0)));
                float s = fmaf(kv, th, kv);
                if (jt * 64 + jl > ig) s = 0.f;   // causal (keep diagonal)
                sv[e] = s;
            }
            sct[il * 33 + (jseg + q) / 2] = h2_(sv[0], sv[1]);
        }
        __syncthreads();

        const int w = tid >> 5, l = tid & 31;
        const int p = (l & 7) * 4 + (l >> 3);   // inverse pair-perm
        char* base = (char*)g_scoreH + ((size_t)(b * L_ + it * 64) * L_ + jt * 64) * 2;
#pragma unroll
        for (int rr = 0; rr < 8; ++rr) {
            const int r = w * 8 + rr;
            *(uint32_t*)(base + (size_t)r * (L_ * 2) + l * 4) = sct[r * 33 + p];
        }
        if (it == jt && it < 31) {   // zero the tile right of the diagonal
            char* zb = (char*)g_scoreH + ((size_t)(b * L_ + it * 64) * L_ + (jt + 1) * 64) * 2;
#pragma unroll
            for (int rr = 0; rr < 8; ++rr) {
                const int r = w * 8 + rr;
                *(uint32_t*)(zb + (size_t)r * (L_ * 2) + l * 4) = 0u;
            }
        }
    } else if (bid < NB_SCORE + NB_EMB) {
        // ---- emb^T (half, pair-permuted along j) ----
        const int idx = (bid - NB_SCORE) * 256 + tid;
        const int l = idx & 31, blk = (idx >> 5) & 31, d = (idx >> 10) & 255, b = idx >> 18;
        const int p = (l & 7) * 4 + (l >> 3);
        const int j = blk * 64 + 2 * p;
        const float f = exp2f(-0.10381025296522991f * (float)d);
        const float a0 = __ldg(&et[b * L_ + j]) * f;
        const float a1 = __ldg(&et[b * L_ + j + 1]) * f;
        const float v0 = (d & 1) ? cosf(a0) : sinf(a0);
        const float v1 = (d & 1) ? cosf(a1) : sinf(a1);
        *(uint32_t*)((char*)g_embTH + ((size_t)(b * 256 + d) * L_ + blk * 64) * 2 + l * 4) =
            h2_(v0, v1);
    } else if (bid < NB_SCORE + NB_EMB + NB_NOISE) {
        // ---- noise (half, pair-permuted along k) ----
        const int idx = (bid - NB_SCORE - NB_EMB) * 256 + tid;
        const int l = idx & 31, blk = (idx >> 5) & 3, row = idx >> 7;
        const int p = (l & 7) * 4 + (l >> 3);
        const int k = blk * 64 + 2 * p;
        const float v0 = __ldg(&noise[(size_t)row * 256 + k]);
        const float v1 = __ldg(&noise[(size_t)row * 256 + k + 1]);
        *(uint32_t*)((char*)g_noiseH + (size_t)row * 512 + blk * 128 + l * 4) = h2_(v0, v1);
    } else {
        // ---- W = [Wn | Wi] rows (half, pair-permuted along k) ----
        const int idx = (bid - NB_SCORE - NB_EMB - NB_NOISE) * 256 + tid;
        const int l = idx & 31, blk = (idx >> 5) & 7, n = idx >> 8;
        const int p = (l & 7) * 4 + (l >> 3);
        const int k = blk * 64 + 2 * p;
        const float v0 = (k < 256) ? __ldg(&Wn[n * 256 + k]) : __ldg(&Wi[n * 256 + k - 256]);
        const float v1 = (k + 1 < 256) ? __ldg(&Wn[n * 256 + k + 1])
                                       : __ldg(&Wi[n * 256 + k + 1 - 256]);
        *(uint32_t*)((char*)g_WpH + (size_t)n * 1024 + blk * 128 + l * 4) = h2_(v0, v1);
    }
}

// ---------------------------------------------------------------------------
// k2: hidden = LN( tril(S) @ E ) — fp16 mma, K=128 chunks, balanced tile-pairs
// ---------------------------------------------------------------------------
__global__ __launch_bounds__(512) void k2_mma(
    const float* __restrict__ gamma, const float* __restrict__ beta)
{
    extern __shared__ char sm[];
    const uint32_t sb = s2u_(sm);
    float* gsm = (float*)(sm + KOFF_PRM);
    float* bsm = gsm + 256;
    float* ps  = (float*)sm;      // alias A0 (only at epilogue)
    float* pq  = ps + 512;

    const int tid = threadIdx.x, lane = tid & 31, warp = tid >> 5;
    const int g = lane >> 2, t = lane & 3, wm = warp >> 2, wn = warp & 3;
    if (tid < 256) { gsm[tid] = gamma[tid]; bsm[tid] = beta[tid]; }

    const int b = blockIdx.y;
    const char* Bbase = (const char*)g_embTH + (size_t)b * D_ * L_ * 2;

    for (int ph = 0; ph < 2; ++ph) {
        const int ib = ph == 0 ? 15 - (int)blockIdx.x : (int)blockIdx.x;
        const int i0 = ib * 128;
        const int nk = ib + 1;                                  // K=128 chunks
        const char* Abase = (const char*)g_scoreH + (size_t)(b * L_ + i0) * L_ * 2;

        auto pref = [&](int kt, uint32_t ao, uint32_t bo) {
            const int j0b = kt * 256;   // byte offset of chunk within row
#pragma unroll
            for (int sub = 0; sub < 2; ++sub) {
                const uint32_t asub = ao + sub * 16384;
                const uint32_t bsub = bo + sub * 32768;
                const int jb = j0b + sub * 128;
#pragma unroll
                for (int q = 0; q < 2; ++q) {
                    const int c = tid + 512 * q;
                    const int r = c >> 3, u = (c & 7) * 16;
                    cpa16_(sb + asub + r * 128 + (u ^ ((r & 7) << 4)),
                           Abase + (size_t)r * (L_ * 2) + jb + u);
                }
#pragma unroll
                for (int q = 0; q < 4; ++q) {
                    const int c = tid + 512 * q;
                    const int n = c >> 3, u = (c & 7) * 16;
                    cpa16_(sb + bsub + n * 128 + (u ^ ((n & 7) << 4)),
                           Bbase + (size_t)n * (L_ * 2) + jb + u);
                }
            }
            CPA_COMMIT_;
        };

        float acc[2][8][4];
#pragma unroll
        for (int mf = 0; mf < 2; ++mf)
#pragma unroll
            for (int nf = 0; nf < 8; ++nf)
#pragma unroll
                for (int e = 0; e < 4; ++e) acc[mf][nf][e] = 0.f;

        __syncthreads();               // params ready / ps-pq alias released
        pref(0, KOFF_A0, KOFF_B0);
        CPA_WAIT0_;
        __syncthreads();

        for (int kt = 0; kt < nk; ++kt) {
            const int s = kt & 1;
            const uint32_t ao = s ? KOFF_A1 : KOFF_A0;
            const uint32_t bo = s ? KOFF_B1 : KOFF_B0;
            if (kt + 1 < nk) pref(kt + 1, s ? KOFF_A0 : KOFF_A1, s ? KOFF_B0 : KOFF_B1);
#pragma unroll
            for (int sub = 0; sub < 2; ++sub) {
                const char* Ab = sm + ao + sub * 16384;
                const char* Bb = sm + bo + sub * 32768;
#pragma unroll
                for (int s2 = 0; s2 < 2; ++s2) {
                    const int toff = t * 32 + s2 * 16;
                    uint4 ar[2][2];
#pragma unroll
                    for (int mf = 0; mf < 2; ++mf) {
                        const int r0 = wm * 32 + mf * 16 + g;
                        ar[mf][0] = *(const uint4*)(Ab + r0 * 128 + (toff ^ ((r0 & 7) << 4)));
                        const int r1 = r0 + 8;
                        ar[mf][1] = *(const uint4*)(Ab + r1 * 128 + (toff ^ ((r1 & 7) << 4)));
                    }
#pragma unroll
                    for (int nf = 0; nf < 8; ++nf) {
                        const int n = wn * 64 + nf * 8 + g;
                        const uint4 br = *(const uint4*)(Bb + n * 128 + (toff ^ ((n & 7) << 4)));
                        mma16_(acc[0][nf], ar[0][0].x, ar[0][1].x, ar[0][0].y, ar[0][1].y, br.x, br.y);
                        mma16_(acc[1][nf], ar[1][0].x, ar[1][1].x, ar[1][0].y, ar[1][1].y, br.x, br.y);
                        mma16_(acc[0][nf], ar[0][0].z, ar[0][1].z, ar[0][0].w, ar[0][1].w, br.z, br.w);
                        mma16_(acc[1][nf], ar[1][0].z, ar[1][1].z, ar[1][0].w, ar[1][1].w, br.z, br.w);
                    }
                }
            }
            CPA_WAIT0_;
            __syncthreads();
        }

        // LN epilogue
#pragma unroll
        for (int mf = 0; mf < 2; ++mf)
#pragma unroll
            for (int h = 0; h < 2; ++h) {
                float s = 0.f, q2 = 0.f;
#pragma unroll
                for (int nf = 0; nf < 8; ++nf) {
                    const float v0 = acc[mf][nf][2 * h], v1 = acc[mf][nf][2 * h + 1];
                    s += v0 + v1;
                    q2 = fmaf(v0, v0, fmaf(v1, v1, q2));
                }
                s  += __shfl_xor_sync(0xffffffffu, s, 1);
                s  += __shfl_xor_sync(0xffffffffu, s, 2);
                q2 += __shfl_xor_sync(0xffffffffu, q2, 1);
                q2 += __shfl_xor_sync(0xffffffffu, q2, 2);
                if (t == 0) {
                    const int r = wm * 32 + mf * 16 + h * 8 + g;
                    ps[r * 4 + wn] = s; pq[r * 4 + wn] = q2;
                }
            }
        __syncthreads();

#pragma unroll
        for (int mf = 0; mf < 2; ++mf)
#pragma unroll
            for (int h = 0; h < 2; ++h) {
                const int r = wm * 32 + mf * 16 + h * 8 + g;
                const float su = ps[r * 4] + ps[r * 4 + 1] + ps[r * 4 + 2] + ps[r * 4 + 3];
                const float sq = pq[r * 4] + pq[r * 4 + 1] + pq[r * 4 + 2] + pq[r * 4 + 3];
                const float mu  = su * (1.f / 256.f);
                const float var = fmaxf(sq * (1.f / 256.f) - mu * mu, 0.f);
                const float rs  = rsqrtf(var + 1e-6f);
                char* dst = (char*)g_hiddenH + (size_t)(b * L_ + i0 + r) * 512;
#pragma unroll
                for (int nf = 0; nf < 8; ++nf) {
                    const int c = wn * 64 + nf * 8 + 2 * t;
                    const float o0 = (acc[mf][nf][2 * h + 0] - mu) * rs * gsm[c] + bsm[c];
                    const float o1 = (acc[mf][nf][2 * h + 1] - mu) * rs * gsm[c + 1] + bsm[c + 1];
                    const int p = (c & 63) >> 1;
                    const int pp = (p & 3) * 8 + (p >> 2);
                    *(uint32_t*)(dst + (c >> 6) * 128 + pp * 4) = h2_(o0, o1);
                }
            }
    }
}

// ---------------------------------------------------------------------------
// k3: out = softplus( w_time . relu([noise|hidden] @ [Wn;Wi]^T) + b )
// K=512 -> 4 chunks of 128.
// ---------------------------------------------------------------------------
__global__ __launch_bounds__(512) void k3_mma(
    const float* __restrict__ wt, const float* __restrict__ btime,
    float* __restrict__ out)
{
    extern __shared__ char sm[];
    const uint32_t sb = s2u_(sm);
    float* wsm = (float*)(sm + KOFF_PRM);
    float* pp  = (float*)sm;   // alias A0 after mainloop

    const int tid = threadIdx.x, lane = tid & 31, warp = tid >> 5;
    const int g = lane >> 2, t = lane & 3, wm = warp >> 2, wn = warp & 3;
    if (tid < 256) wsm[tid] = wt[tid];

    const int b  = blockIdx.y;
    const int i0 = blockIdx.x * 128;

    auto pref = [&](int kt, uint32_t ao, uint32_t bo) {
#pragma unroll
        for (int sub = 0; sub < 2; ++sub) {
            const int ko = 2 * kt + sub;     // 64-wide sub-chunk index (0..7)
            const uint32_t asub = ao + sub * 16384;
            const uint32_t bsub = bo + sub * 32768;
            const char* Asrc = (ko < 4)
                ? (const char*)g_noiseH + (size_t)(b * L_ + i0) * 512 + ko * 128
                : (const char*)g_hiddenH + (size_t)(b * L_ + i0) * 512 + (ko - 4) * 128;
#pragma unroll
            for (int q = 0; q < 2; ++q) {
                const int c = tid + 512 * q;
                const int r = c >> 3, u = (c & 7) * 16;
                cpa16_(sb + asub + r * 128 + (u ^ ((r & 7) << 4)), Asrc + (size_t)r * 512 + u);
            }
#pragma unroll
            for (int q = 0; q < 4; ++q) {
                const int c = tid + 512 * q;
                const int n = c >> 3, u = (c & 7) * 16;
                cpa16_(sb + bsub + n * 128 + (u ^ ((n & 7) << 4)),
                       (const char*)g_WpH + (size_t)n * 1024 + ko * 128 + u);
            }
        }
        CPA_COMMIT_;
    };

    float acc[2][8][4];
#pragma unroll
    for (int mf = 0; mf < 2; ++mf)
#pragma unroll
        for (int nf = 0; nf < 8; ++nf)
#pragma unroll
            for (int e = 0; e < 4; ++e) acc[mf][nf][e] = 0.f;

    __syncthreads();
    pref(0, KOFF_A0, KOFF_B0);
    CPA_WAIT0_;
    __syncthreads();

    for (int kt = 0; kt < 4; ++kt) {
        const int s = kt & 1;
        const uint32_t ao = s ? KOFF_A1 : KOFF_A0;
        const uint32_t bo = s ? KOFF_B1 : KOFF_B0;
        if (kt < 3) pref(kt + 1, s ? KOFF_A0 : KOFF_A1, s ? KOFF_B0 : KOFF_B1);
#pragma unroll
        for (int sub = 0; sub < 2; ++sub) {
            const char* Ab = sm + ao + sub * 16384;
            const char* Bb = sm + bo + sub * 32768;
#pragma unroll
            for (int s2 = 0; s2 < 2; ++s2) {
                const int toff = t * 32 + s2 * 16;
                uint4 ar[2][2];
#pragma unroll
                for (int mf = 0; mf < 2; ++mf) {
                    const int r0 = wm * 32 + mf * 16 + g;
                    ar[mf][0] = *(const uint4*)(Ab + r0 * 128 + (toff ^ ((r0 & 7) << 4)));
                    const int r1 = r0 + 8;
                    ar[mf][1] = *(const uint4*)(Ab + r1 * 128 + (toff ^ ((r1 & 7) << 4)));
                }
#pragma unroll
                for (int nf = 0; nf < 8; ++nf) {
                    const int n = wn * 64 + nf * 8 + g;
                    const uint4 br = *(const uint4*)(Bb + n * 128 + (toff ^ ((n & 7) << 4)));
                    mma16_(acc[0][nf], ar[0][0].x, ar[0][1].x, ar[0][0].y, ar[0][1].y, br.x, br.y);
                    mma16_(acc[1][nf], ar[1][0].x, ar[1][1].x, ar[1][0].y, ar[1][1].y, br.x, br.y);
                    mma16_(acc[0][nf], ar[0][0].z, ar[0][1].z, ar[0][0].w, ar[0][1].w, br.z, br.w);
                    mma16_(acc[1][nf], ar[1][0].z, ar[1][1].z, ar[1][0].w, ar[1][1].w, br.z, br.w);
                }
            }
        }
        CPA_WAIT0_;
        __syncthreads();
    }

    // epilogue: relu + dot(w_time) partials -> quad reduce -> smem -> softplus
#pragma unroll
    for (int mf = 0; mf < 2; ++mf)
#pragma unroll
        for (int h = 0; h < 2; ++h) {
            float p = 0.f;
#pragma unroll
            for (int nf = 0; nf < 8; ++nf)
#pragma unroll
                for (int e = 0; e < 2; ++e) {
                    const int c = wn * 64 + nf * 8 + 2 * t + e;
                    p = fmaf(wsm[c], fmaxf(acc[mf][nf][2 * h + e], 0.f), p);
                }
            p += __shfl_xor_sync(0xffffffffu, p, 1);
            p += __shfl_xor_sync(0xffffffffu, p, 2);
            if (t == 0) pp[(wm * 32 + mf * 16 + h * 8 + g) * 4 + wn] = p;
        }
    __syncthreads();
    if (tid < 128) {
        const float s = pp[tid * 4] + pp[tid * 4 + 1] + pp[tid * 4 + 2] + pp[tid * 4 + 3];
        out[b * L_ + i0 + tid] = softplusf_(s + btime[0]);
    }
}

// ---------------------------------------------------------------------------
// Input order: 0 event_type (unused), 1 event_time, 2 noise, 3 gate_params,
// 4 length_scale, 5 Wn, 6 Wi, 7 w_time, 8 b_time, 9 ln_gamma, 10 ln_beta.
// ---------------------------------------------------------------------------
extern "C" void kernel_launch(void* const* d_in, const int* in_sizes, int n_in,
                              void* d_out, int out_size) {
    const float* et    = (const float*)d_in[1];
    const float* noise = (const float*)d_in[2];
    const float* gp    = (const float*)d_in[3];
    const float* lsc   = (const float*)d_in[4];
    const float* Wn    = (const float*)d_in[5];
    const float* Wi    = (const float*)d_in[6];
    const float* wt    = (const float*)d_in[7];
    const float* bt    = (const float*)d_in[8];
    const float* gam   = (const float*)d_in[9];
    const float* bet   = (const float*)d_in[10];
    float* out = (float*)d_out;

    cudaFuncSetAttribute(k2_mma, cudaFuncAttributeMaxDynamicSharedMemorySize, KSM_TOT);
    cudaFuncSetAttribute(k3_mma, cudaFuncAttributeMaxDynamicSharedMemorySize, KSM_TOT);

    prep_kernel<<<NB_TOT, 256>>>(et, gp, lsc, noise, Wn, Wi);
    k2_mma<<<dim3(8, B_), 512, KSM_TOT>>>(gam, bet);
    k3_mma<<<dim3(16, B_), 512, KSM_TOT>>>(wt, bt, out);
}